// round 2
// baseline (speedup 1.0000x reference)
#include <cuda_runtime.h>
#include <cuda_bf16.h>
#include <math.h>

#define N_NODES 100000
#define N_EDGES 1600000
#define N_GRAPHS 2048
#define DIM 128
#define OUT_DIM 12
#define N_LAYERS 5
#define BN_EPS 1e-5f

// ---------------- scratch (device globals; no allocation allowed) ----------------
__device__ __align__(16) float g_h[(size_t)N_NODES * DIM];
__device__ __align__(16) float g_z[(size_t)N_NODES * DIM];
__device__ __align__(16) float g_t[(size_t)N_NODES * DIM];
__device__ __align__(16) float g_stats[2 * DIM];   // [0:128) sums, [128:256) sumsq
__device__ __align__(16) float g_scale[DIM];
__device__ __align__(16) float g_shift[DIM];
__device__ __align__(16) float g_pool[(size_t)N_GRAPHS * DIM];

// ---------------- small utility kernels ----------------
__global__ void zero_kernel(float* p, int n4) {
    int i = blockIdx.x * blockDim.x + threadIdx.x;
    if (i < n4) ((float4*)p)[i] = make_float4(0.f, 0.f, 0.f, 0.f);
}

__global__ void copy_kernel(const float* __restrict__ src, float* __restrict__ dst, int n4) {
    int i = blockIdx.x * blockDim.x + threadIdx.x;
    if (i < n4) ((float4*)dst)[i] = ((const float4*)src)[i];
}

// ---------------- edge scatter-add: z[dst] += h[src], one warp per edge ----------------
__global__ void edge_kernel(const float* __restrict__ h,
                            const int* __restrict__ src,
                            const int* __restrict__ dst,
                            float* __restrict__ z) {
    int warp = (blockIdx.x * blockDim.x + threadIdx.x) >> 5;
    int lane = threadIdx.x & 31;
    if (warp >= N_EDGES) return;
    int s = src[warp];
    int d = dst[warp];
    float4 v = *(const float4*)(h + (size_t)s * DIM + lane * 4);
    float* p = z + (size_t)d * DIM + lane * 4;
    asm volatile("red.global.add.v4.f32 [%0], {%1,%2,%3,%4};"
                 :: "l"(p), "f"(v.x), "f"(v.y), "f"(v.z), "f"(v.w) : "memory");
}

// ---------------- GEMM: C[M,128] = act(A[M,128] @ W[128,128] + b) ----------------
// block = 256 threads (16x16), tile = 64 rows x 128 cols, micro-tile 4x8
__global__ void mlp_gemm(const float* __restrict__ A,
                         const float* __restrict__ W,
                         const float* __restrict__ bias,
                         float* __restrict__ C,
                         int M, int do_relu) {
    extern __shared__ float sm[];
    float* Ws = sm;               // 128*128
    float* As = sm + DIM * DIM;   // 64*132 (padded)
    const int tid = threadIdx.x;
    const int tx = tid & 15;
    const int ty = tid >> 4;
    const int row0 = blockIdx.x * 64;

    // load W (16384 floats) via float4
    for (int i = tid * 4; i < DIM * DIM; i += 256 * 4)
        *(float4*)(Ws + i) = *(const float4*)(W + i);
    // load A tile (64 rows x 32 float4) with zero-pad for OOB rows
    for (int i = tid; i < 64 * 32; i += 256) {
        int r = i >> 5, c4 = i & 31;
        float4 v = make_float4(0.f, 0.f, 0.f, 0.f);
        if (row0 + r < M) v = *(const float4*)(A + (size_t)(row0 + r) * DIM + c4 * 4);
        *(float4*)(As + r * 132 + c4 * 4) = v;
    }
    __syncthreads();

    float acc[4][8];
#pragma unroll
    for (int i = 0; i < 4; i++)
#pragma unroll
        for (int j = 0; j < 8; j++) acc[i][j] = 0.f;

#pragma unroll 4
    for (int k = 0; k < DIM; k++) {
        float a[4], b[8];
#pragma unroll
        for (int i = 0; i < 4; i++) a[i] = As[(ty * 4 + i) * 132 + k];
        float4 b0 = *(float4*)(Ws + k * DIM + tx * 8);
        float4 b1 = *(float4*)(Ws + k * DIM + tx * 8 + 4);
        b[0] = b0.x; b[1] = b0.y; b[2] = b0.z; b[3] = b0.w;
        b[4] = b1.x; b[5] = b1.y; b[6] = b1.z; b[7] = b1.w;
#pragma unroll
        for (int i = 0; i < 4; i++)
#pragma unroll
            for (int j = 0; j < 8; j++) acc[i][j] = fmaf(a[i], b[j], acc[i][j]);
    }

    // epilogue: bias (+ optional relu), store
    float4 bb0 = *(const float4*)(bias + tx * 8);
    float4 bb1 = *(const float4*)(bias + tx * 8 + 4);
    float bv[8] = {bb0.x, bb0.y, bb0.z, bb0.w, bb1.x, bb1.y, bb1.z, bb1.w};
#pragma unroll
    for (int i = 0; i < 4; i++) {
        int r = row0 + ty * 4 + i;
        if (r >= M) continue;
        float o[8];
#pragma unroll
        for (int j = 0; j < 8; j++) {
            o[j] = acc[i][j] + bv[j];
            if (do_relu) o[j] = fmaxf(o[j], 0.f);
        }
        *(float4*)(C + (size_t)r * DIM + tx * 8)     = make_float4(o[0], o[1], o[2], o[3]);
        *(float4*)(C + (size_t)r * DIM + tx * 8 + 4) = make_float4(o[4], o[5], o[6], o[7]);
    }
}

// ---------------- BatchNorm ----------------
__global__ void bn_stats(const float* __restrict__ z, float* stats) {
    int col = threadIdx.x;  // 128 threads
    float s = 0.f, s2 = 0.f;
    for (int r = blockIdx.x; r < N_NODES; r += gridDim.x) {
        float v = z[(size_t)r * DIM + col];
        s += v; s2 += v * v;
    }
    atomicAdd(&stats[col], s);
    atomicAdd(&stats[DIM + col], s2);
}

__global__ void bn_finalize(const float* __restrict__ stats,
                            const float* __restrict__ gamma,
                            const float* __restrict__ beta,
                            float* scale, float* shift) {
    int c = threadIdx.x;
    float mean = stats[c] / (float)N_NODES;
    float var = stats[DIM + c] / (float)N_NODES - mean * mean;
    float sc = gamma[c] * rsqrtf(var + BN_EPS);
    scale[c] = sc;
    shift[c] = beta[c] - mean * sc;
}

__global__ void bn_apply(const float* __restrict__ z,
                         const float* __restrict__ scale,
                         const float* __restrict__ shift,
                         float* __restrict__ h, int n4) {
    int i = blockIdx.x * blockDim.x + threadIdx.x;
    if (i >= n4) return;
    int c = (i * 4) & (DIM - 1);
    float4 v = ((const float4*)z)[i];
    float4 sc = *(const float4*)(scale + c);
    float4 sh = *(const float4*)(shift + c);
    float4 o;
    o.x = fmaxf(fmaf(v.x, sc.x, sh.x), 0.f);
    o.y = fmaxf(fmaf(v.y, sc.y, sh.y), 0.f);
    o.z = fmaxf(fmaf(v.z, sc.z, sh.z), 0.f);
    o.w = fmaxf(fmaf(v.w, sc.w, sh.w), 0.f);
    ((float4*)h)[i] = o;
}

// ---------------- global_add_pool: one warp per node ----------------
__global__ void pool_kernel(const float* __restrict__ h,
                            const int* __restrict__ batch,
                            float* __restrict__ pool) {
    int node = (blockIdx.x * blockDim.x + threadIdx.x) >> 5;
    int lane = threadIdx.x & 31;
    if (node >= N_NODES) return;
    int b = batch[node];
    float4 v = *(const float4*)(h + (size_t)node * DIM + lane * 4);
    float* p = pool + (size_t)b * DIM + lane * 4;
    asm volatile("red.global.add.v4.f32 [%0], {%1,%2,%3,%4};"
                 :: "l"(p), "f"(v.x), "f"(v.y), "f"(v.z), "f"(v.w) : "memory");
}

// ---------------- head MLP: out = relu(g @ Wh1 + bh1) @ Wh2 + bh2 ----------------
__global__ void head_kernel(const float* __restrict__ pool,
                            const float* __restrict__ Wh1, const float* __restrict__ bh1,
                            const float* __restrict__ Wh2, const float* __restrict__ bh2,
                            float* __restrict__ out) {
    __shared__ float row[DIM];
    __shared__ float hid[DIM];
    int g = blockIdx.x;
    int t = threadIdx.x;  // 128
    row[t] = pool[(size_t)g * DIM + t];
    __syncthreads();
    float acc = bh1[t];
    for (int k = 0; k < DIM; k++) acc = fmaf(row[k], Wh1[k * DIM + t], acc);
    hid[t] = fmaxf(acc, 0.f);
    __syncthreads();
    if (t < OUT_DIM) {
        float o = bh2[t];
        for (int k = 0; k < DIM; k++) o = fmaf(hid[k], Wh2[k * OUT_DIM + t], o);
        out[(size_t)g * OUT_DIM + t] = o;
    }
}

// ---------------- launch ----------------
extern "C" void kernel_launch(void* const* d_in, const int* in_sizes, int n_in,
                              void* d_out, int out_size) {
    const float* x     = (const float*)d_in[0];
    const int*   ei    = (const int*)d_in[1];
    const int*   batch = (const int*)d_in[2];
    const float* W1s = (const float*)d_in[3];
    const float* b1s = (const float*)d_in[4];
    const float* W2s = (const float*)d_in[5];
    const float* b2s = (const float*)d_in[6];
    const float* gammas = (const float*)d_in[7];
    const float* betas  = (const float*)d_in[8];
    const float* Wh1 = (const float*)d_in[9];
    const float* bh1 = (const float*)d_in[10];
    const float* Wh2 = (const float*)d_in[11];
    const float* bh2 = (const float*)d_in[12];
    float* out = (float*)d_out;

    float *hp, *zp, *tp, *statsp, *scalep, *shiftp, *poolp;
    cudaGetSymbolAddress((void**)&hp, g_h);
    cudaGetSymbolAddress((void**)&zp, g_z);
    cudaGetSymbolAddress((void**)&tp, g_t);
    cudaGetSymbolAddress((void**)&statsp, g_stats);
    cudaGetSymbolAddress((void**)&scalep, g_scale);
    cudaGetSymbolAddress((void**)&shiftp, g_shift);
    cudaGetSymbolAddress((void**)&poolp, g_pool);

    const int* src = ei;
    const int* dst = ei + N_EDGES;

    const int nfeat4 = N_NODES * DIM / 4;                 // 3.2M float4
    const int copyBlocks = (nfeat4 + 255) / 256;
    const int edgeBlocks = (N_EDGES * 32 + 255) / 256;
    const int gemmBlocks = (N_NODES + 63) / 64;
    const int gemmSmem = (DIM * DIM + 64 * 132) * sizeof(float);
    cudaFuncSetAttribute(mlp_gemm, cudaFuncAttributeMaxDynamicSharedMemorySize, gemmSmem);

    for (int l = 0; l < N_LAYERS; l++) {
        const float* hin = (l == 0) ? x : hp;
        // z = h + segment_sum(h[src], dst)
        copy_kernel<<<copyBlocks, 256>>>(hin, zp, nfeat4);
        edge_kernel<<<edgeBlocks, 256>>>(hin, src, dst, zp);
        // t = relu(z @ W1 + b1); z = t @ W2 + b2
        mlp_gemm<<<gemmBlocks, 256, gemmSmem>>>(zp, W1s + (size_t)l * DIM * DIM,
                                                b1s + (size_t)l * DIM, tp, N_NODES, 1);
        mlp_gemm<<<gemmBlocks, 256, gemmSmem>>>(tp, W2s + (size_t)l * DIM * DIM,
                                                b2s + (size_t)l * DIM, zp, N_NODES, 0);
        // batchnorm + relu -> h
        zero_kernel<<<1, 64>>>(statsp, 64);  // 256 floats = 64 float4
        bn_stats<<<1024, DIM>>>(zp, statsp);
        bn_finalize<<<1, DIM>>>(statsp, gammas + (size_t)l * DIM, betas + (size_t)l * DIM,
                                scalep, shiftp);
        bn_apply<<<copyBlocks, 256>>>(zp, scalep, shiftp, hp, nfeat4);
    }

    // global_add_pool
    const int pool4 = N_GRAPHS * DIM / 4;
    zero_kernel<<<(pool4 + 255) / 256, 256>>>(poolp, pool4);
    pool_kernel<<<(N_NODES * 32 + 255) / 256, 256>>>(hp, batch, poolp);

    // head
    head_kernel<<<N_GRAPHS, DIM>>>(poolp, Wh1, bh1, Wh2, bh2, out);
}

// round 5
// speedup vs baseline: 1.4586x; 1.4586x over previous
#include <cuda_runtime.h>
#include <cuda_bf16.h>
#include <math.h>

#define N_NODES 100000
#define N_EDGES 1600000
#define N_GRAPHS 2048
#define DIM 128
#define OUT_DIM 12
#define N_LAYERS 5
#define BN_EPS 1e-5f

// ---------------- scratch (device globals; no allocation allowed) ----------------
__device__ __align__(16) float g_h[(size_t)N_NODES * DIM];
__device__ __align__(16) float g_z[(size_t)N_NODES * DIM];
__device__ __align__(16) float g_t[(size_t)N_NODES * DIM];
__device__ __align__(16) float g_stats[2 * DIM];   // [0:128) sums, [128:256) sumsq
__device__ __align__(16) float g_scale[DIM];
__device__ __align__(16) float g_shift[DIM];
__device__ __align__(16) float g_pool[(size_t)N_GRAPHS * DIM];

// ---------------- small utility kernels ----------------
__global__ void zero_kernel(float* p, int n4) {
    int i = blockIdx.x * blockDim.x + threadIdx.x;
    if (i < n4) ((float4*)p)[i] = make_float4(0.f, 0.f, 0.f, 0.f);
}

__global__ void copy_kernel(const float* __restrict__ src, float* __restrict__ dst, int n4) {
    int i = blockIdx.x * blockDim.x + threadIdx.x;
    if (i < n4) ((float4*)dst)[i] = ((const float4*)src)[i];
}

// ---------------- edge scatter-add: z[dst] += h[src], one warp per edge ----------------
__global__ void edge_kernel(const float* __restrict__ h,
                            const int* __restrict__ src,
                            const int* __restrict__ dst,
                            float* __restrict__ z) {
    int warp = (blockIdx.x * blockDim.x + threadIdx.x) >> 5;
    int lane = threadIdx.x & 31;
    if (warp >= N_EDGES) return;
    int s = src[warp];
    int d = dst[warp];
    float4 v = *(const float4*)(h + (size_t)s * DIM + lane * 4);
    float* p = z + (size_t)d * DIM + lane * 4;
    asm volatile("red.global.add.v4.f32 [%0], {%1,%2,%3,%4};"
                 :: "l"(p), "f"(v.x), "f"(v.y), "f"(v.z), "f"(v.w) : "memory");
}

// ---------------- tf32 helpers ----------------
// cvt.rna.tf32.f32 needs a .b32 destination
__device__ __forceinline__ unsigned cvt_tf32(float x) {
    unsigned r;
    asm("cvt.rna.tf32.f32 %0, %1;" : "=r"(r) : "f"(x));
    return r;
}

// A/B fragments are .b32 regs; accumulators are .f32.
__device__ __forceinline__ void mma_tf32(float* d, const unsigned* a, const unsigned* b) {
    asm volatile(
        "mma.sync.aligned.m16n8k8.row.col.f32.tf32.tf32.f32 "
        "{%0,%1,%2,%3}, {%4,%5,%6,%7}, {%8,%9}, {%0,%1,%2,%3};"
        : "+f"(d[0]), "+f"(d[1]), "+f"(d[2]), "+f"(d[3])
        : "r"(a[0]), "r"(a[1]), "r"(a[2]), "r"(a[3]), "r"(b[0]), "r"(b[1]));
}

// ---------------- tf32 tensor-core GEMM: C[M,128] = act(A[M,128] @ W[128,128] + b) ----
// 256 threads = 8 warps; block tile 64x128; warp tile 32x32 (2 m-tiles x 4 n-tiles of
// m16n8k8); A and W converted to tf32 once during smem fill (stored as b32 patterns).
#define AS_STRIDE 132
#define WS_STRIDE 132
__global__ void mlp_gemm_tc(const float* __restrict__ A,
                            const float* __restrict__ W,
                            const float* __restrict__ bias,
                            float* __restrict__ C,
                            int M, int do_relu) {
    extern __shared__ unsigned smu[];
    unsigned* Ws = smu;                     // 128 x 132
    unsigned* As = smu + DIM * WS_STRIDE;   // 64 x 132
    const int tid = threadIdx.x;
    const int warp = tid >> 5;
    const int lane = tid & 31;
    const int row0 = blockIdx.x * 64;

    // load + convert W [k=128][n=128]
    for (int i = tid; i < DIM * DIM / 4; i += 256) {
        int r = i >> 5, c4 = (i & 31) * 4;
        float4 v = *(const float4*)(W + r * DIM + c4);
        unsigned* p = Ws + r * WS_STRIDE + c4;
        p[0] = cvt_tf32(v.x); p[1] = cvt_tf32(v.y);
        p[2] = cvt_tf32(v.z); p[3] = cvt_tf32(v.w);
    }
    // load + convert A tile [64][128], zero-pad OOB rows
    for (int i = tid; i < 64 * 32; i += 256) {
        int r = i >> 5, c4 = (i & 31) * 4;
        float4 v = make_float4(0.f, 0.f, 0.f, 0.f);
        if (row0 + r < M) v = *(const float4*)(A + (size_t)(row0 + r) * DIM + c4);
        unsigned* p = As + r * AS_STRIDE + c4;
        p[0] = cvt_tf32(v.x); p[1] = cvt_tf32(v.y);
        p[2] = cvt_tf32(v.z); p[3] = cvt_tf32(v.w);
    }
    __syncthreads();

    const int wm = (warp >> 2) * 32;   // 0 or 32
    const int wn = (warp & 3) * 32;    // 0,32,64,96
    const int lq = lane >> 2;          // 0..7
    const int lr = lane & 3;           // 0..3

    float acc[2][4][4];
#pragma unroll
    for (int i = 0; i < 2; i++)
#pragma unroll
        for (int j = 0; j < 4; j++)
#pragma unroll
            for (int q = 0; q < 4; q++) acc[i][j][q] = 0.f;

#pragma unroll
    for (int ks = 0; ks < 16; ks++) {
        const int k0 = ks * 8;
        unsigned af[2][4];
#pragma unroll
        for (int i = 0; i < 2; i++) {
            const unsigned* base = As + (wm + i * 16 + lq) * AS_STRIDE + k0 + lr;
            af[i][0] = base[0];
            af[i][1] = base[8 * AS_STRIDE];
            af[i][2] = base[4];
            af[i][3] = base[8 * AS_STRIDE + 4];
        }
        unsigned bf[4][2];
#pragma unroll
        for (int j = 0; j < 4; j++) {
            const unsigned* base = Ws + (k0 + lr) * WS_STRIDE + wn + j * 8 + lq;
            bf[j][0] = base[0];
            bf[j][1] = base[4 * WS_STRIDE];
        }
#pragma unroll
        for (int i = 0; i < 2; i++)
#pragma unroll
            for (int j = 0; j < 4; j++) mma_tf32(acc[i][j], af[i], bf[j]);
    }

    // epilogue: bias (+relu), store. c0,c1 at (row, col), c2,c3 at (row+8, col)
#pragma unroll
    for (int i = 0; i < 2; i++) {
#pragma unroll
        for (int j = 0; j < 4; j++) {
            int col = wn + j * 8 + lr * 2;
            float b0 = bias[col], b1 = bias[col + 1];
            int r0 = row0 + wm + i * 16 + lq;
            float2 v0, v1;
            v0.x = acc[i][j][0] + b0; v0.y = acc[i][j][1] + b1;
            v1.x = acc[i][j][2] + b0; v1.y = acc[i][j][3] + b1;
            if (do_relu) {
                v0.x = fmaxf(v0.x, 0.f); v0.y = fmaxf(v0.y, 0.f);
                v1.x = fmaxf(v1.x, 0.f); v1.y = fmaxf(v1.y, 0.f);
            }
            if (r0 < M)     *(float2*)(C + (size_t)r0 * DIM + col) = v0;
            if (r0 + 8 < M) *(float2*)(C + (size_t)(r0 + 8) * DIM + col) = v1;
        }
    }
}

// ---------------- BatchNorm ----------------
__global__ void bn_stats(const float* __restrict__ z, float* stats) {
    int col = threadIdx.x;  // 128 threads
    float s = 0.f, s2 = 0.f;
    for (int r = blockIdx.x; r < N_NODES; r += gridDim.x) {
        float v = z[(size_t)r * DIM + col];
        s += v; s2 += v * v;
    }
    atomicAdd(&stats[col], s);
    atomicAdd(&stats[DIM + col], s2);
}

__global__ void bn_finalize(const float* __restrict__ stats,
                            const float* __restrict__ gamma,
                            const float* __restrict__ beta,
                            float* scale, float* shift) {
    int c = threadIdx.x;
    float mean = stats[c] / (float)N_NODES;
    float var = stats[DIM + c] / (float)N_NODES - mean * mean;
    float sc = gamma[c] * rsqrtf(var + BN_EPS);
    scale[c] = sc;
    shift[c] = beta[c] - mean * sc;
}

__global__ void bn_apply(const float* __restrict__ z,
                         const float* __restrict__ scale,
                         const float* __restrict__ shift,
                         float* __restrict__ h, int n4) {
    int i = blockIdx.x * blockDim.x + threadIdx.x;
    if (i >= n4) return;
    int c = (i * 4) & (DIM - 1);
    float4 v = ((const float4*)z)[i];
    float4 sc = *(const float4*)(scale + c);
    float4 sh = *(const float4*)(shift + c);
    float4 o;
    o.x = fmaxf(fmaf(v.x, sc.x, sh.x), 0.f);
    o.y = fmaxf(fmaf(v.y, sc.y, sh.y), 0.f);
    o.z = fmaxf(fmaf(v.z, sc.z, sh.z), 0.f);
    o.w = fmaxf(fmaf(v.w, sc.w, sh.w), 0.f);
    ((float4*)h)[i] = o;
}

// ---------------- global_add_pool: one warp per node ----------------
__global__ void pool_kernel(const float* __restrict__ h,
                            const int* __restrict__ batch,
                            float* __restrict__ pool) {
    int node = (blockIdx.x * blockDim.x + threadIdx.x) >> 5;
    int lane = threadIdx.x & 31;
    if (node >= N_NODES) return;
    int b = batch[node];
    float4 v = *(const float4*)(h + (size_t)node * DIM + lane * 4);
    float* p = pool + (size_t)b * DIM + lane * 4;
    asm volatile("red.global.add.v4.f32 [%0], {%1,%2,%3,%4};"
                 :: "l"(p), "f"(v.x), "f"(v.y), "f"(v.z), "f"(v.w) : "memory");
}

// ---------------- head MLP: out = relu(g @ Wh1 + bh1) @ Wh2 + bh2 ----------------
__global__ void head_kernel(const float* __restrict__ pool,
                            const float* __restrict__ Wh1, const float* __restrict__ bh1,
                            const float* __restrict__ Wh2, const float* __restrict__ bh2,
                            float* __restrict__ out) {
    __shared__ float row[DIM];
    __shared__ float hid[DIM];
    int g = blockIdx.x;
    int t = threadIdx.x;  // 128
    row[t] = pool[(size_t)g * DIM + t];
    __syncthreads();
    float acc = bh1[t];
    for (int k = 0; k < DIM; k++) acc = fmaf(row[k], Wh1[k * DIM + t], acc);
    hid[t] = fmaxf(acc, 0.f);
    __syncthreads();
    if (t < OUT_DIM) {
        float o = bh2[t];
        for (int k = 0; k < DIM; k++) o = fmaf(hid[k], Wh2[k * OUT_DIM + t], o);
        out[(size_t)g * OUT_DIM + t] = o;
    }
}

// ---------------- launch ----------------
extern "C" void kernel_launch(void* const* d_in, const int* in_sizes, int n_in,
                              void* d_out, int out_size) {
    const float* x     = (const float*)d_in[0];
    const int*   ei    = (const int*)d_in[1];
    const int*   batch = (const int*)d_in[2];
    const float* W1s = (const float*)d_in[3];
    const float* b1s = (const float*)d_in[4];
    const float* W2s = (const float*)d_in[5];
    const float* b2s = (const float*)d_in[6];
    const float* gammas = (const float*)d_in[7];
    const float* betas  = (const float*)d_in[8];
    const float* Wh1 = (const float*)d_in[9];
    const float* bh1 = (const float*)d_in[10];
    const float* Wh2 = (const float*)d_in[11];
    const float* bh2 = (const float*)d_in[12];
    float* out = (float*)d_out;

    float *hp, *zp, *tp, *statsp, *scalep, *shiftp, *poolp;
    cudaGetSymbolAddress((void**)&hp, g_h);
    cudaGetSymbolAddress((void**)&zp, g_z);
    cudaGetSymbolAddress((void**)&tp, g_t);
    cudaGetSymbolAddress((void**)&statsp, g_stats);
    cudaGetSymbolAddress((void**)&scalep, g_scale);
    cudaGetSymbolAddress((void**)&shiftp, g_shift);
    cudaGetSymbolAddress((void**)&poolp, g_pool);

    const int* src = ei;
    const int* dst = ei + N_EDGES;

    const int nfeat4 = N_NODES * DIM / 4;                 // 3.2M float4
    const int copyBlocks = (nfeat4 + 255) / 256;
    const int edgeBlocks = (N_EDGES * 32 + 255) / 256;
    const int gemmBlocks = (N_NODES + 63) / 64;
    const int gemmSmem = (DIM * WS_STRIDE + 64 * AS_STRIDE) * sizeof(float);
    cudaFuncSetAttribute(mlp_gemm_tc, cudaFuncAttributeMaxDynamicSharedMemorySize, gemmSmem);

    for (int l = 0; l < N_LAYERS; l++) {
        const float* hin = (l == 0) ? x : hp;
        // z = h + segment_sum(h[src], dst)
        copy_kernel<<<copyBlocks, 256>>>(hin, zp, nfeat4);
        edge_kernel<<<edgeBlocks, 256>>>(hin, src, dst, zp);
        // t = relu(z @ W1 + b1); z = t @ W2 + b2
        mlp_gemm_tc<<<gemmBlocks, 256, gemmSmem>>>(zp, W1s + (size_t)l * DIM * DIM,
                                                   b1s + (size_t)l * DIM, tp, N_NODES, 1);
        mlp_gemm_tc<<<gemmBlocks, 256, gemmSmem>>>(tp, W2s + (size_t)l * DIM * DIM,
                                                   b2s + (size_t)l * DIM, zp, N_NODES, 0);
        // batchnorm + relu -> h
        zero_kernel<<<1, 64>>>(statsp, 64);  // 256 floats = 64 float4
        bn_stats<<<1024, DIM>>>(zp, statsp);
        bn_finalize<<<1, DIM>>>(statsp, gammas + (size_t)l * DIM, betas + (size_t)l * DIM,
                                scalep, shiftp);
        bn_apply<<<copyBlocks, 256>>>(zp, scalep, shiftp, hp, nfeat4);
    }

    // global_add_pool
    const int pool4 = N_GRAPHS * DIM / 4;
    zero_kernel<<<(pool4 + 255) / 256, 256>>>(poolp, pool4);
    pool_kernel<<<(N_NODES * 32 + 255) / 256, 256>>>(hp, batch, poolp);

    // head
    head_kernel<<<N_GRAPHS, DIM>>>(poolp, Wh1, bh1, Wh2, bh2, out);
}

// round 6
// speedup vs baseline: 1.4953x; 1.0252x over previous
#include <cuda_runtime.h>
#include <cuda_bf16.h>
#include <math.h>

#define N_NODES 100000
#define N_EDGES 1600000
#define N_GRAPHS 2048
#define DIM 128
#define OUT_DIM 12
#define N_LAYERS 5
#define BN_EPS 1e-5f

// ---------------- scratch (device globals; no allocation allowed) ----------------
__device__ __align__(16) float g_h[(size_t)N_NODES * DIM];
__device__ __align__(16) float g_z[(size_t)N_NODES * DIM];
__device__ __align__(16) float g_t[(size_t)N_NODES * DIM];
__device__ __align__(16) float g_stats[2 * DIM];   // [0:128) sums, [128:256) sumsq
__device__ __align__(16) float g_scale[DIM];
__device__ __align__(16) float g_shift[DIM];
__device__ __align__(16) float g_pool[(size_t)N_GRAPHS * DIM];
__device__ __align__(16) unsigned g_wcvt[(size_t)2 * N_LAYERS * DIM * DIM];  // tf32 weights

// ---------------- small utility kernels ----------------
__global__ void zero_kernel(float* p, int n4) {
    int i = blockIdx.x * blockDim.x + threadIdx.x;
    if (i < n4) ((float4*)p)[i] = make_float4(0.f, 0.f, 0.f, 0.f);
}

// ---------------- tf32 helpers ----------------
__device__ __forceinline__ unsigned cvt_tf32(float x) {
    unsigned r;
    asm("cvt.rna.tf32.f32 %0, %1;" : "=r"(r) : "f"(x));
    return r;
}

__device__ __forceinline__ void mma_tf32(float* d, const unsigned* a, const unsigned* b) {
    asm volatile(
        "mma.sync.aligned.m16n8k8.row.col.f32.tf32.tf32.f32 "
        "{%0,%1,%2,%3}, {%4,%5,%6,%7}, {%8,%9}, {%0,%1,%2,%3};"
        : "+f"(d[0]), "+f"(d[1]), "+f"(d[2]), "+f"(d[3])
        : "r"(a[0]), "r"(a[1]), "r"(a[2]), "r"(a[3]), "r"(b[0]), "r"(b[1]));
}

// pre-convert all layer weights to tf32 bit patterns (once per call)
__global__ void wcvt_kernel(const float* __restrict__ W1s, const float* __restrict__ W2s) {
    const int total = N_LAYERS * DIM * DIM;
    int i = blockIdx.x * blockDim.x + threadIdx.x;
    if (i < total) {
        g_wcvt[i] = cvt_tf32(W1s[i]);
        g_wcvt[total + i] = cvt_tf32(W2s[i]);
    }
}

// ---------------- edge scatter-add: z[dst] += h[src], one warp per edge ----------------
__global__ void edge_kernel(const float* __restrict__ h,
                            const int* __restrict__ src,
                            const int* __restrict__ dst,
                            float* __restrict__ z) {
    int warp = (blockIdx.x * blockDim.x + threadIdx.x) >> 5;
    int lane = threadIdx.x & 31;
    if (warp >= N_EDGES) return;
    int s = src[warp];
    int d = dst[warp];
    float4 v = *(const float4*)(h + (size_t)s * DIM + lane * 4);
    float* p = z + (size_t)d * DIM + lane * 4;
    asm volatile("red.global.add.v4.f32 [%0], {%1,%2,%3,%4};"
                 :: "l"(p), "f"(v.x), "f"(v.y), "f"(v.z), "f"(v.w) : "memory");
}

// ---------------- tf32 tensor-core GEMM ----------------
// C[M,128] = act((A [+ A2]) @ W + b); optional fused column sum/sumsq into stats.
// 256 threads = 8 warps; block tile 64x128; warp tile 32x32.
#define AS_STRIDE 132
#define WS_STRIDE 132
__global__ void mlp_gemm_tc(const float* __restrict__ A,
                            const float* __restrict__ A2,     // nullable: added to A
                            const unsigned* __restrict__ Wc,  // pre-converted tf32
                            const float* __restrict__ bias,
                            float* __restrict__ C,
                            int M, int do_relu,
                            float* __restrict__ stats) {      // nullable: fused bn stats
    extern __shared__ unsigned smu[];
    unsigned* Ws = smu;                     // 128 x 132
    unsigned* As = smu + DIM * WS_STRIDE;   // 64 x 132
    const int tid = threadIdx.x;
    const int warp = tid >> 5;
    const int lane = tid & 31;
    const int row0 = blockIdx.x * 64;

    // copy pre-converted W [k=128][n=128] (b32, no cvt)
    for (int i = tid; i < DIM * DIM / 4; i += 256) {
        int r = i >> 5, c4 = (i & 31) * 4;
        uint4 v = *(const uint4*)(Wc + r * DIM + c4);
        unsigned* p = Ws + r * WS_STRIDE + c4;
        p[0] = v.x; p[1] = v.y; p[2] = v.z; p[3] = v.w;
    }
    // load + (optional add) + convert A tile [64][128], zero-pad OOB rows
    for (int i = tid; i < 64 * 32; i += 256) {
        int r = i >> 5, c4 = (i & 31) * 4;
        float4 v = make_float4(0.f, 0.f, 0.f, 0.f);
        if (row0 + r < M) {
            v = *(const float4*)(A + (size_t)(row0 + r) * DIM + c4);
            if (A2) {
                float4 w = *(const float4*)(A2 + (size_t)(row0 + r) * DIM + c4);
                v.x += w.x; v.y += w.y; v.z += w.z; v.w += w.w;
            }
        }
        unsigned* p = As + r * AS_STRIDE + c4;
        p[0] = cvt_tf32(v.x); p[1] = cvt_tf32(v.y);
        p[2] = cvt_tf32(v.z); p[3] = cvt_tf32(v.w);
    }
    __syncthreads();

    const int wm = (warp >> 2) * 32;   // 0 or 32
    const int wn = (warp & 3) * 32;    // 0,32,64,96
    const int lq = lane >> 2;          // 0..7
    const int lr = lane & 3;           // 0..3

    float acc[2][4][4];
#pragma unroll
    for (int i = 0; i < 2; i++)
#pragma unroll
        for (int j = 0; j < 4; j++)
#pragma unroll
            for (int q = 0; q < 4; q++) acc[i][j][q] = 0.f;

#pragma unroll
    for (int ks = 0; ks < 16; ks++) {
        const int k0 = ks * 8;
        unsigned af[2][4];
#pragma unroll
        for (int i = 0; i < 2; i++) {
            const unsigned* base = As + (wm + i * 16 + lq) * AS_STRIDE + k0 + lr;
            af[i][0] = base[0];
            af[i][1] = base[8 * AS_STRIDE];
            af[i][2] = base[4];
            af[i][3] = base[8 * AS_STRIDE + 4];
        }
        unsigned bf[4][2];
#pragma unroll
        for (int j = 0; j < 4; j++) {
            const unsigned* base = Ws + (k0 + lr) * WS_STRIDE + wn + j * 8 + lq;
            bf[j][0] = base[0];
            bf[j][1] = base[4 * WS_STRIDE];
        }
#pragma unroll
        for (int i = 0; i < 2; i++)
#pragma unroll
            for (int j = 0; j < 4; j++) mma_tf32(acc[i][j], af[i], bf[j]);
    }

    // epilogue: bias (+relu), store; optional column sum/sumsq accumulation
    float csum[8], csq[8];
#pragma unroll
    for (int k = 0; k < 8; k++) { csum[k] = 0.f; csq[k] = 0.f; }

#pragma unroll
    for (int i = 0; i < 2; i++) {
#pragma unroll
        for (int j = 0; j < 4; j++) {
            int col = wn + j * 8 + lr * 2;
            float b0 = bias[col], b1 = bias[col + 1];
            int r0 = row0 + wm + i * 16 + lq;
            float2 v0, v1;
            v0.x = acc[i][j][0] + b0; v0.y = acc[i][j][1] + b1;
            v1.x = acc[i][j][2] + b0; v1.y = acc[i][j][3] + b1;
            if (do_relu) {
                v0.x = fmaxf(v0.x, 0.f); v0.y = fmaxf(v0.y, 0.f);
                v1.x = fmaxf(v1.x, 0.f); v1.y = fmaxf(v1.y, 0.f);
            }
            bool ok0 = r0 < M, ok1 = r0 + 8 < M;
            if (ok0) *(float2*)(C + (size_t)r0 * DIM + col) = v0;
            if (ok1) *(float2*)(C + (size_t)(r0 + 8) * DIM + col) = v1;
            if (stats) {
                float s0 = (ok0 ? v0.x : 0.f) + (ok1 ? v1.x : 0.f);
                float s1 = (ok0 ? v0.y : 0.f) + (ok1 ? v1.y : 0.f);
                float q0 = (ok0 ? v0.x * v0.x : 0.f) + (ok1 ? v1.x * v1.x : 0.f);
                float q1 = (ok0 ? v0.y * v0.y : 0.f) + (ok1 ? v1.y * v1.y : 0.f);
                csum[j * 2]     += s0; csq[j * 2]     += q0;
                csum[j * 2 + 1] += s1; csq[j * 2 + 1] += q1;
            }
        }
    }

    if (stats) {
        // reduce over lq (lane bits [2:5)) via shfl_xor; lanes with lq==0 hold totals
#pragma unroll
        for (int k = 0; k < 8; k++) {
#pragma unroll
            for (int off = 4; off < 32; off <<= 1) {
                csum[k] += __shfl_xor_sync(0xffffffff, csum[k], off);
                csq[k]  += __shfl_xor_sync(0xffffffff, csq[k], off);
            }
        }
        if (lq == 0) {
#pragma unroll
            for (int k = 0; k < 8; k++) {
                int col = wn + (k >> 1) * 8 + lr * 2 + (k & 1);
                atomicAdd(&stats[col], csum[k]);
                atomicAdd(&stats[DIM + col], csq[k]);
            }
        }
    }
}

// ---------------- BatchNorm finalize + apply ----------------
__global__ void bn_finalize(const float* __restrict__ stats,
                            const float* __restrict__ gamma,
                            const float* __restrict__ beta,
                            float* scale, float* shift) {
    int c = threadIdx.x;
    float mean = stats[c] / (float)N_NODES;
    float var = stats[DIM + c] / (float)N_NODES - mean * mean;
    float sc = gamma[c] * rsqrtf(var + BN_EPS);
    scale[c] = sc;
    shift[c] = beta[c] - mean * sc;
}

__global__ void bn_apply(const float* __restrict__ z,
                         const float* __restrict__ scale,
                         const float* __restrict__ shift,
                         float* __restrict__ h, int n4) {
    int i = blockIdx.x * blockDim.x + threadIdx.x;
    if (i >= n4) return;
    int c = (i * 4) & (DIM - 1);
    float4 v = ((const float4*)z)[i];
    float4 sc = *(const float4*)(scale + c);
    float4 sh = *(const float4*)(shift + c);
    float4 o;
    o.x = fmaxf(fmaf(v.x, sc.x, sh.x), 0.f);
    o.y = fmaxf(fmaf(v.y, sc.y, sh.y), 0.f);
    o.z = fmaxf(fmaf(v.z, sc.z, sh.z), 0.f);
    o.w = fmaxf(fmaf(v.w, sc.w, sh.w), 0.f);
    ((float4*)h)[i] = o;
}

// ---------------- global_add_pool: one warp per node ----------------
__global__ void pool_kernel(const float* __restrict__ h,
                            const int* __restrict__ batch,
                            float* __restrict__ pool) {
    int node = (blockIdx.x * blockDim.x + threadIdx.x) >> 5;
    int lane = threadIdx.x & 31;
    if (node >= N_NODES) return;
    int b = batch[node];
    float4 v = *(const float4*)(h + (size_t)node * DIM + lane * 4);
    float* p = pool + (size_t)b * DIM + lane * 4;
    asm volatile("red.global.add.v4.f32 [%0], {%1,%2,%3,%4};"
                 :: "l"(p), "f"(v.x), "f"(v.y), "f"(v.z), "f"(v.w) : "memory");
}

// ---------------- head MLP: out = relu(g @ Wh1 + bh1) @ Wh2 + bh2 ----------------
__global__ void head_kernel(const float* __restrict__ pool,
                            const float* __restrict__ Wh1, const float* __restrict__ bh1,
                            const float* __restrict__ Wh2, const float* __restrict__ bh2,
                            float* __restrict__ out) {
    __shared__ float row[DIM];
    __shared__ float hid[DIM];
    int g = blockIdx.x;
    int t = threadIdx.x;  // 128
    row[t] = pool[(size_t)g * DIM + t];
    __syncthreads();
    float acc = bh1[t];
    for (int k = 0; k < DIM; k++) acc = fmaf(row[k], Wh1[k * DIM + t], acc);
    hid[t] = fmaxf(acc, 0.f);
    __syncthreads();
    if (t < OUT_DIM) {
        float o = bh2[t];
        for (int k = 0; k < DIM; k++) o = fmaf(hid[k], Wh2[k * OUT_DIM + t], o);
        out[(size_t)g * OUT_DIM + t] = o;
    }
}

// ---------------- launch ----------------
extern "C" void kernel_launch(void* const* d_in, const int* in_sizes, int n_in,
                              void* d_out, int out_size) {
    const float* x     = (const float*)d_in[0];
    const int*   ei    = (const int*)d_in[1];
    const int*   batch = (const int*)d_in[2];
    const float* W1s = (const float*)d_in[3];
    const float* b1s = (const float*)d_in[4];
    const float* W2s = (const float*)d_in[5];
    const float* b2s = (const float*)d_in[6];
    const float* gammas = (const float*)d_in[7];
    const float* betas  = (const float*)d_in[8];
    const float* Wh1 = (const float*)d_in[9];
    const float* bh1 = (const float*)d_in[10];
    const float* Wh2 = (const float*)d_in[11];
    const float* bh2 = (const float*)d_in[12];
    float* out = (float*)d_out;

    float *hp, *zp, *tp, *statsp, *scalep, *shiftp, *poolp;
    unsigned* wcp;
    cudaGetSymbolAddress((void**)&hp, g_h);
    cudaGetSymbolAddress((void**)&zp, g_z);
    cudaGetSymbolAddress((void**)&tp, g_t);
    cudaGetSymbolAddress((void**)&statsp, g_stats);
    cudaGetSymbolAddress((void**)&scalep, g_scale);
    cudaGetSymbolAddress((void**)&shiftp, g_shift);
    cudaGetSymbolAddress((void**)&poolp, g_pool);
    cudaGetSymbolAddress((void**)&wcp, g_wcvt);

    const int* src = ei;
    const int* dst = ei + N_EDGES;

    const int nfeat4 = N_NODES * DIM / 4;                 // 3.2M float4
    const int copyBlocks = (nfeat4 + 255) / 256;
    const int edgeBlocks = (N_EDGES * 32 + 255) / 256;
    const int gemmBlocks = (N_NODES + 63) / 64;
    const int gemmSmem = (DIM * WS_STRIDE + 64 * AS_STRIDE) * sizeof(unsigned);
    const int wTotal = N_LAYERS * DIM * DIM;
    cudaFuncSetAttribute(mlp_gemm_tc, cudaFuncAttributeMaxDynamicSharedMemorySize, gemmSmem);

    // pre-convert all weights to tf32 (one pass)
    wcvt_kernel<<<(wTotal + 255) / 256, 256>>>(W1s, W2s);

    for (int l = 0; l < N_LAYERS; l++) {
        const float* hin = (l == 0) ? x : hp;
        // agg = segment_sum(h[src], dst) into zeroed z
        zero_kernel<<<copyBlocks, 256>>>(zp, nfeat4);
        edge_kernel<<<edgeBlocks, 256>>>(hin, src, dst, zp);
        // t = relu((agg + h) @ W1 + b1)
        mlp_gemm_tc<<<gemmBlocks, 256, gemmSmem>>>(
            zp, hin, wcp + (size_t)l * DIM * DIM,
            b1s + (size_t)l * DIM, tp, N_NODES, 1, nullptr);
        // z = t @ W2 + b2, with fused column stats
        zero_kernel<<<1, 64>>>(statsp, 64);  // 256 floats = 64 float4
        mlp_gemm_tc<<<gemmBlocks, 256, gemmSmem>>>(
            tp, nullptr, wcp + (size_t)(wTotal + l * DIM * DIM),
            b2s + (size_t)l * DIM, zp, N_NODES, 0, statsp);
        // batchnorm + relu -> h
        bn_finalize<<<1, DIM>>>(statsp, gammas + (size_t)l * DIM, betas + (size_t)l * DIM,
                                scalep, shiftp);
        bn_apply<<<copyBlocks, 256>>>(zp, scalep, shiftp, hp, nfeat4);
    }

    // global_add_pool
    const int pool4 = N_GRAPHS * DIM / 4;
    zero_kernel<<<(pool4 + 255) / 256, 256>>>(poolp, pool4);
    pool_kernel<<<(N_NODES * 32 + 255) / 256, 256>>>(hp, batch, poolp);

    // head
    head_kernel<<<N_GRAPHS, DIM>>>(poolp, Wh1, bh1, Wh2, bh2, out);
}

// round 7
// speedup vs baseline: 1.6670x; 1.1148x over previous
#include <cuda_runtime.h>
#include <cuda_bf16.h>
#include <math.h>

#define N_NODES 100000
#define N_EDGES 1600000
#define N_GRAPHS 2048
#define DIM 128
#define OUT_DIM 12
#define N_LAYERS 5
#define BN_EPS 1e-5f
#define TILE_ROWS 64
#define AS_STRIDE 132
#define WS_STRIDE 132
#define GEMM_BLOCKS 148

// ---------------- scratch (device globals; no allocation allowed) ----------------
__device__ __align__(16) float g_agg[(size_t)N_NODES * DIM];
__device__ __align__(16) float g_z[(size_t)N_NODES * DIM];
__device__ __align__(16) float g_t[(size_t)N_NODES * DIM];
__device__ __align__(16) float g_stats[2 * DIM];   // [0:128) sums, [128:256) sumsq
__device__ __align__(16) float g_scale[DIM];
__device__ __align__(16) float g_shift[DIM];
__device__ __align__(16) float g_pool[(size_t)N_GRAPHS * DIM];
__device__ __align__(16) unsigned g_wcvt[(size_t)2 * N_LAYERS * DIM * DIM];  // tf32 weights

// ---------------- small utility kernels ----------------
__global__ void zero_kernel(float* p, int n4) {
    int i = blockIdx.x * blockDim.x + threadIdx.x;
    if (i < n4) ((float4*)p)[i] = make_float4(0.f, 0.f, 0.f, 0.f);
}

// ---------------- tf32 helpers ----------------
__device__ __forceinline__ unsigned cvt_tf32(float x) {
    unsigned r;
    asm("cvt.rna.tf32.f32 %0, %1;" : "=r"(r) : "f"(x));
    return r;
}

__device__ __forceinline__ void mma_tf32(float* d, const unsigned* a, const unsigned* b) {
    asm volatile(
        "mma.sync.aligned.m16n8k8.row.col.f32.tf32.tf32.f32 "
        "{%0,%1,%2,%3}, {%4,%5,%6,%7}, {%8,%9}, {%0,%1,%2,%3};"
        : "+f"(d[0]), "+f"(d[1]), "+f"(d[2]), "+f"(d[3])
        : "r"(a[0]), "r"(a[1]), "r"(a[2]), "r"(a[3]), "r"(b[0]), "r"(b[1]));
}

// pre-convert all layer weights to tf32 bit patterns (once per call)
__global__ void wcvt_kernel(const float* __restrict__ W1s, const float* __restrict__ W2s) {
    const int total = N_LAYERS * DIM * DIM;
    int i = blockIdx.x * blockDim.x + threadIdx.x;
    if (i < total) {
        g_wcvt[i] = cvt_tf32(W1s[i]);
        g_wcvt[total + i] = cvt_tf32(W2s[i]);
    }
}

// ---------------- init: agg = bnrelu(z)  (or raw copy for layer 0) ----------------
__global__ void init_kernel(const float* __restrict__ z,
                            const float* __restrict__ scale,
                            const float* __restrict__ shift,
                            float* __restrict__ agg, int raw, int n4) {
    int i = blockIdx.x * blockDim.x + threadIdx.x;
    if (i >= n4) return;
    float4 v = ((const float4*)z)[i];
    if (!raw) {
        int c = (i * 4) & (DIM - 1);
        float4 sc = *(const float4*)(scale + c);
        float4 sh = *(const float4*)(shift + c);
        v.x = fmaxf(fmaf(v.x, sc.x, sh.x), 0.f);
        v.y = fmaxf(fmaf(v.y, sc.y, sh.y), 0.f);
        v.z = fmaxf(fmaf(v.z, sc.z, sh.z), 0.f);
        v.w = fmaxf(fmaf(v.w, sc.w, sh.w), 0.f);
    }
    ((float4*)agg)[i] = v;
}

// ---------------- edge scatter-add: agg[dst] += bnrelu(z[src]) ----------------
__global__ void edge_kernel(const float* __restrict__ z,
                            const float* __restrict__ scale,
                            const float* __restrict__ shift,
                            int raw,
                            const int* __restrict__ src,
                            const int* __restrict__ dst,
                            float* __restrict__ agg) {
    int warp = (blockIdx.x * blockDim.x + threadIdx.x) >> 5;
    int lane = threadIdx.x & 31;
    if (warp >= N_EDGES) return;
    int s = src[warp];
    int d = dst[warp];
    float4 v = *(const float4*)(z + (size_t)s * DIM + lane * 4);
    if (!raw) {
        float4 sc = *(const float4*)(scale + lane * 4);
        float4 sh = *(const float4*)(shift + lane * 4);
        v.x = fmaxf(fmaf(v.x, sc.x, sh.x), 0.f);
        v.y = fmaxf(fmaf(v.y, sc.y, sh.y), 0.f);
        v.z = fmaxf(fmaf(v.z, sc.z, sh.z), 0.f);
        v.w = fmaxf(fmaf(v.w, sc.w, sh.w), 0.f);
    }
    float* p = agg + (size_t)d * DIM + lane * 4;
    asm volatile("red.global.add.v4.f32 [%0], {%1,%2,%3,%4};"
                 :: "l"(p), "f"(v.x), "f"(v.y), "f"(v.z), "f"(v.w) : "memory");
}

// ---------------- persistent tf32 tensor-core GEMM ----------------
// C[M,128] = act(A[M,128] @ W + b); W resident in smem per block; A tiles
// double-buffered via cp.async. 256 threads = 8 warps; warp tile 32x32.
__global__ void mlp_gemm_tc(const float* __restrict__ A,
                            const unsigned* __restrict__ Wc,
                            const float* __restrict__ bias,
                            float* __restrict__ C,
                            int M, int do_relu,
                            float* __restrict__ stats,
                            int ntiles) {
    extern __shared__ unsigned smu[];
    unsigned* Ws = smu;                                 // 128 x 132 (tf32 bits)
    float* Ab0 = (float*)(smu + DIM * WS_STRIDE);       // 64 x 132 raw fp32
    float* Ab1 = Ab0 + TILE_ROWS * AS_STRIDE;
    const int tid = threadIdx.x;
    const int warp = tid >> 5;
    const int lane = tid & 31;

    // W resident: copy pre-converted tf32 once
    for (int i = tid; i < DIM * DIM / 4; i += 256) {
        int r = i >> 5, c4 = (i & 31) * 4;
        uint4 v = *(const uint4*)(Wc + r * DIM + c4);
        unsigned* p = Ws + r * WS_STRIDE + c4;
        p[0] = v.x; p[1] = v.y; p[2] = v.z; p[3] = v.w;
    }

    const int wm = (warp >> 2) * 32;
    const int wn = (warp & 3) * 32;
    const int lq = lane >> 2;
    const int lr = lane & 3;

    // prefetch first tile
    int t = blockIdx.x;
    {
        float* dstb = Ab0;
        if (t < ntiles) {
            const float* base = A + (size_t)t * TILE_ROWS * DIM;
            int maxrow = M - t * TILE_ROWS;
#pragma unroll
            for (int q = 0; q < 8; q++) {
                int idx = q * 256 + tid;
                int r = idx >> 5, c4 = (idx & 31) * 4;
                unsigned saddr = (unsigned)__cvta_generic_to_shared(dstb + r * AS_STRIDE + c4);
                const float* g = base + (r < maxrow ? r : 0) * DIM + c4;
                int sz = (r < maxrow) ? 16 : 0;
                asm volatile("cp.async.cg.shared.global [%0], [%1], 16, %2;"
                             :: "r"(saddr), "l"(g), "r"(sz));
            }
        }
        asm volatile("cp.async.commit_group;");
    }

    int buf = 0;
    for (; t < ntiles; t += GEMM_BLOCKS) {
        // prefetch next tile into other buffer
        int nxt = t + GEMM_BLOCKS;
        float* dstb = buf ? Ab0 : Ab1;
        if (nxt < ntiles) {
            const float* base = A + (size_t)nxt * TILE_ROWS * DIM;
            int maxrow = M - nxt * TILE_ROWS;
#pragma unroll
            for (int q = 0; q < 8; q++) {
                int idx = q * 256 + tid;
                int r = idx >> 5, c4 = (idx & 31) * 4;
                unsigned saddr = (unsigned)__cvta_generic_to_shared(dstb + r * AS_STRIDE + c4);
                const float* g = base + (r < maxrow ? r : 0) * DIM + c4;
                int sz = (r < maxrow) ? 16 : 0;
                asm volatile("cp.async.cg.shared.global [%0], [%1], 16, %2;"
                             :: "r"(saddr), "l"(g), "r"(sz));
            }
        }
        asm volatile("cp.async.commit_group;");
        asm volatile("cp.async.wait_group 1;");
        __syncthreads();  // current buffer ready (also orders W on first pass)

        const float* Ac = buf ? Ab1 : Ab0;
        const int row0 = t * TILE_ROWS;

        float acc[2][4][4];
#pragma unroll
        for (int i = 0; i < 2; i++)
#pragma unroll
            for (int j = 0; j < 4; j++)
#pragma unroll
                for (int q = 0; q < 4; q++) acc[i][j][q] = 0.f;

#pragma unroll
        for (int ks = 0; ks < 16; ks++) {
            const int k0 = ks * 8;
            unsigned af[2][4];
#pragma unroll
            for (int i = 0; i < 2; i++) {
                const float* base = Ac + (wm + i * 16 + lq) * AS_STRIDE + k0 + lr;
                af[i][0] = cvt_tf32(base[0]);
                af[i][1] = cvt_tf32(base[8 * AS_STRIDE]);
                af[i][2] = cvt_tf32(base[4]);
                af[i][3] = cvt_tf32(base[8 * AS_STRIDE + 4]);
            }
            unsigned bf[4][2];
#pragma unroll
            for (int j = 0; j < 4; j++) {
                const unsigned* base = Ws + (k0 + lr) * WS_STRIDE + wn + j * 8 + lq;
                bf[j][0] = base[0];
                bf[j][1] = base[4 * WS_STRIDE];
            }
#pragma unroll
            for (int i = 0; i < 2; i++)
#pragma unroll
                for (int j = 0; j < 4; j++) mma_tf32(acc[i][j], af[i], bf[j]);
        }

        // epilogue: bias (+relu), store; optional fused bn stats
        float csum[8], csq[8];
#pragma unroll
        for (int k = 0; k < 8; k++) { csum[k] = 0.f; csq[k] = 0.f; }

#pragma unroll
        for (int i = 0; i < 2; i++) {
#pragma unroll
            for (int j = 0; j < 4; j++) {
                int col = wn + j * 8 + lr * 2;
                float b0 = bias[col], b1 = bias[col + 1];
                int r0 = row0 + wm + i * 16 + lq;
                float2 v0, v1;
                v0.x = acc[i][j][0] + b0; v0.y = acc[i][j][1] + b1;
                v1.x = acc[i][j][2] + b0; v1.y = acc[i][j][3] + b1;
                if (do_relu) {
                    v0.x = fmaxf(v0.x, 0.f); v0.y = fmaxf(v0.y, 0.f);
                    v1.x = fmaxf(v1.x, 0.f); v1.y = fmaxf(v1.y, 0.f);
                }
                bool ok0 = r0 < M, ok1 = r0 + 8 < M;
                if (ok0) *(float2*)(C + (size_t)r0 * DIM + col) = v0;
                if (ok1) *(float2*)(C + (size_t)(r0 + 8) * DIM + col) = v1;
                if (stats) {
                    csum[j * 2]     += (ok0 ? v0.x : 0.f) + (ok1 ? v1.x : 0.f);
                    csum[j * 2 + 1] += (ok0 ? v0.y : 0.f) + (ok1 ? v1.y : 0.f);
                    csq[j * 2]      += (ok0 ? v0.x * v0.x : 0.f) + (ok1 ? v1.x * v1.x : 0.f);
                    csq[j * 2 + 1]  += (ok0 ? v0.y * v0.y : 0.f) + (ok1 ? v1.y * v1.y : 0.f);
                }
            }
        }
        if (stats) {
#pragma unroll
            for (int k = 0; k < 8; k++) {
#pragma unroll
                for (int off = 4; off < 32; off <<= 1) {
                    csum[k] += __shfl_xor_sync(0xffffffff, csum[k], off);
                    csq[k]  += __shfl_xor_sync(0xffffffff, csq[k], off);
                }
            }
            if (lq == 0) {
#pragma unroll
                for (int k = 0; k < 8; k++) {
                    int col = wn + (k >> 1) * 8 + lr * 2 + (k & 1);
                    atomicAdd(&stats[col], csum[k]);
                    atomicAdd(&stats[DIM + col], csq[k]);
                }
            }
        }
        __syncthreads();  // all warps done reading current buffer before it is refilled
        buf ^= 1;
    }
}

// ---------------- BatchNorm finalize ----------------
__global__ void bn_finalize(const float* __restrict__ stats,
                            const float* __restrict__ gamma,
                            const float* __restrict__ beta,
                            float* scale, float* shift) {
    int c = threadIdx.x;
    float mean = stats[c] / (float)N_NODES;
    float var = stats[DIM + c] / (float)N_NODES - mean * mean;
    float sc = gamma[c] * rsqrtf(var + BN_EPS);
    scale[c] = sc;
    shift[c] = beta[c] - mean * sc;
}

// ---------------- global_add_pool with fused bnrelu: one warp per node -----------
__global__ void pool_kernel(const float* __restrict__ z,
                            const float* __restrict__ scale,
                            const float* __restrict__ shift,
                            const int* __restrict__ batch,
                            float* __restrict__ pool) {
    int node = (blockIdx.x * blockDim.x + threadIdx.x) >> 5;
    int lane = threadIdx.x & 31;
    if (node >= N_NODES) return;
    int b = batch[node];
    float4 v = *(const float4*)(z + (size_t)node * DIM + lane * 4);
    float4 sc = *(const float4*)(scale + lane * 4);
    float4 sh = *(const float4*)(shift + lane * 4);
    v.x = fmaxf(fmaf(v.x, sc.x, sh.x), 0.f);
    v.y = fmaxf(fmaf(v.y, sc.y, sh.y), 0.f);
    v.z = fmaxf(fmaf(v.z, sc.z, sh.z), 0.f);
    v.w = fmaxf(fmaf(v.w, sc.w, sh.w), 0.f);
    float* p = pool + (size_t)b * DIM + lane * 4;
    asm volatile("red.global.add.v4.f32 [%0], {%1,%2,%3,%4};"
                 :: "l"(p), "f"(v.x), "f"(v.y), "f"(v.z), "f"(v.w) : "memory");
}

// ---------------- head MLP: out = relu(g @ Wh1 + bh1) @ Wh2 + bh2 ----------------
__global__ void head_kernel(const float* __restrict__ pool,
                            const float* __restrict__ Wh1, const float* __restrict__ bh1,
                            const float* __restrict__ Wh2, const float* __restrict__ bh2,
                            float* __restrict__ out) {
    __shared__ float row[DIM];
    __shared__ float hid[DIM];
    int g = blockIdx.x;
    int t = threadIdx.x;  // 128
    row[t] = pool[(size_t)g * DIM + t];
    __syncthreads();
    float acc = bh1[t];
    for (int k = 0; k < DIM; k++) acc = fmaf(row[k], Wh1[k * DIM + t], acc);
    hid[t] = fmaxf(acc, 0.f);
    __syncthreads();
    if (t < OUT_DIM) {
        float o = bh2[t];
        for (int k = 0; k < DIM; k++) o = fmaf(hid[k], Wh2[k * OUT_DIM + t], o);
        out[(size_t)g * OUT_DIM + t] = o;
    }
}

// ---------------- launch ----------------
extern "C" void kernel_launch(void* const* d_in, const int* in_sizes, int n_in,
                              void* d_out, int out_size) {
    const float* x     = (const float*)d_in[0];
    const int*   ei    = (const int*)d_in[1];
    const int*   batch = (const int*)d_in[2];
    const float* W1s = (const float*)d_in[3];
    const float* b1s = (const float*)d_in[4];
    const float* W2s = (const float*)d_in[5];
    const float* b2s = (const float*)d_in[6];
    const float* gammas = (const float*)d_in[7];
    const float* betas  = (const float*)d_in[8];
    const float* Wh1 = (const float*)d_in[9];
    const float* bh1 = (const float*)d_in[10];
    const float* Wh2 = (const float*)d_in[11];
    const float* bh2 = (const float*)d_in[12];
    float* out = (float*)d_out;

    float *aggp, *zp, *tp, *statsp, *scalep, *shiftp, *poolp;
    unsigned* wcp;
    cudaGetSymbolAddress((void**)&aggp, g_agg);
    cudaGetSymbolAddress((void**)&zp, g_z);
    cudaGetSymbolAddress((void**)&tp, g_t);
    cudaGetSymbolAddress((void**)&statsp, g_stats);
    cudaGetSymbolAddress((void**)&scalep, g_scale);
    cudaGetSymbolAddress((void**)&shiftp, g_shift);
    cudaGetSymbolAddress((void**)&poolp, g_pool);
    cudaGetSymbolAddress((void**)&wcp, g_wcvt);

    const int* src = ei;
    const int* dst = ei + N_EDGES;

    const int nfeat4 = N_NODES * DIM / 4;
    const int strBlocks = (nfeat4 + 255) / 256;
    const int edgeBlocks = (N_EDGES * 32 + 255) / 256;
    const int ntiles = (N_NODES + TILE_ROWS - 1) / TILE_ROWS;
    const int gemmSmem = (DIM * WS_STRIDE + 2 * TILE_ROWS * AS_STRIDE) * sizeof(unsigned);
    const int wTotal = N_LAYERS * DIM * DIM;
    cudaFuncSetAttribute(mlp_gemm_tc, cudaFuncAttributeMaxDynamicSharedMemorySize, gemmSmem);

    // pre-convert all weights to tf32 (one pass)
    wcvt_kernel<<<(wTotal + 255) / 256, 256>>>(W1s, W2s);

    for (int l = 0; l < N_LAYERS; l++) {
        const float* zin = (l == 0) ? x : zp;
        int raw = (l == 0) ? 1 : 0;
        // agg = h (self term), then agg[dst] += h[src], h = bnrelu(z_prev) on the fly
        init_kernel<<<strBlocks, 256>>>(zin, scalep, shiftp, aggp, raw, nfeat4);
        edge_kernel<<<edgeBlocks, 256>>>(zin, scalep, shiftp, raw, src, dst, aggp);
        // t = relu(agg @ W1 + b1)
        mlp_gemm_tc<<<GEMM_BLOCKS, 256, gemmSmem>>>(
            aggp, wcp + (size_t)l * DIM * DIM,
            b1s + (size_t)l * DIM, tp, N_NODES, 1, nullptr, ntiles);
        // z = t @ W2 + b2, fused column stats
        zero_kernel<<<1, 64>>>(statsp, 64);
        mlp_gemm_tc<<<GEMM_BLOCKS, 256, gemmSmem>>>(
            tp, wcp + (size_t)(wTotal + l * DIM * DIM),
            b2s + (size_t)l * DIM, zp, N_NODES, 0, statsp, ntiles);
        // bn scale/shift for this layer (consumed by next layer / pool)
        bn_finalize<<<1, DIM>>>(statsp, gammas + (size_t)l * DIM, betas + (size_t)l * DIM,
                                scalep, shiftp);
    }

    // global_add_pool of bnrelu(z_final)
    const int pool4 = N_GRAPHS * DIM / 4;
    zero_kernel<<<(pool4 + 255) / 256, 256>>>(poolp, pool4);
    pool_kernel<<<(N_NODES * 32 + 255) / 256, 256>>>(zp, scalep, shiftp, batch, poolp);

    // head
    head_kernel<<<N_GRAPHS, DIM>>>(poolp, Wh1, bh1, Wh2, bh2, out);
}

// round 8
// speedup vs baseline: 2.5185x; 1.5108x over previous
#include <cuda_runtime.h>
#include <cuda_bf16.h>
#include <math.h>

#define N_NODES 100000
#define N_EDGES 1600000
#define N_GRAPHS 2048
#define DIM 128
#define OUT_DIM 12
#define N_LAYERS 5
#define BN_EPS 1e-5f
#define TILE_ROWS 64
#define AS_STRIDE 132
#define WS_STRIDE 132
#define GEMM_BLOCKS 148
#define SCAN_B 1024
#define SCAN_NB ((N_NODES + SCAN_B - 1) / SCAN_B)   // 98

// ---------------- scratch (device globals; no allocation allowed) ----------------
__device__ __align__(16) float g_agg[(size_t)N_NODES * DIM];
__device__ __align__(16) float g_z[(size_t)N_NODES * DIM];
__device__ __align__(16) float g_t[(size_t)N_NODES * DIM];
__device__ __align__(16) float g_stats[2 * DIM];
__device__ __align__(16) float g_scale[DIM];
__device__ __align__(16) float g_shift[DIM];
__device__ __align__(16) float g_pool[(size_t)N_GRAPHS * DIM];
__device__ __align__(16) unsigned g_wcvt[(size_t)2 * N_LAYERS * DIM * DIM];
// CSR scratch
__device__ __align__(16) int g_deg[N_NODES];
__device__ __align__(16) int g_beg[N_NODES];
__device__ __align__(16) int g_cur[N_NODES];
__device__ __align__(16) int g_bsum[SCAN_NB];
__device__ __align__(16) int g_csrsrc[N_EDGES];

// ---------------- small utility kernels ----------------
__global__ void zero_kernel(float* p, int n4) {
    int i = blockIdx.x * blockDim.x + threadIdx.x;
    if (i < n4) ((float4*)p)[i] = make_float4(0.f, 0.f, 0.f, 0.f);
}

__global__ void zero_int_kernel(int* p, int n) {
    int i = blockIdx.x * blockDim.x + threadIdx.x;
    if (i < n) p[i] = 0;
}

// ---------------- CSR build ----------------
__global__ void count_kernel(const int* __restrict__ dst) {
    int i = blockIdx.x * blockDim.x + threadIdx.x;
    if (i < N_EDGES) atomicAdd(&g_deg[dst[i]], 1);
}

__global__ void scan_block_kernel() {
    __shared__ int sm[SCAN_B];
    int tid = threadIdx.x;
    int i = blockIdx.x * SCAN_B + tid;
    int v = (i < N_NODES) ? g_deg[i] : 0;
    sm[tid] = v;
    __syncthreads();
    for (int off = 1; off < SCAN_B; off <<= 1) {
        int t = (tid >= off) ? sm[tid - off] : 0;
        __syncthreads();
        sm[tid] += t;
        __syncthreads();
    }
    if (i < N_NODES) g_beg[i] = sm[tid] - v;   // exclusive within block
    if (tid == SCAN_B - 1) g_bsum[blockIdx.x] = sm[tid];
}

__global__ void scan_totals_kernel() {
    if (threadIdx.x == 0) {
        int run = 0;
        for (int i = 0; i < SCAN_NB; i++) { int t = g_bsum[i]; g_bsum[i] = run; run += t; }
    }
}

__global__ void scan_add_kernel() {
    int i = blockIdx.x * SCAN_B + threadIdx.x;
    if (i < N_NODES) {
        int b = g_beg[i] + g_bsum[blockIdx.x];
        g_beg[i] = b;
        g_cur[i] = b;
    }
}

__global__ void fill_kernel(const int* __restrict__ src, const int* __restrict__ dst) {
    int i = blockIdx.x * blockDim.x + threadIdx.x;
    if (i < N_EDGES) {
        int slot = atomicAdd(&g_cur[dst[i]], 1);
        g_csrsrc[slot] = src[i];
    }
}

// ---------------- fused aggregation: agg[n] = h[n] + sum_{e: dst=n} h[src] ------
// h = bnrelu(z) applied on the fly (raw=1 for layer 0: h = z). One warp per node.
__global__ void agg_kernel(const float* __restrict__ z,
                           const float* __restrict__ scale,
                           const float* __restrict__ shift,
                           int raw,
                           float* __restrict__ agg) {
    int node = (blockIdx.x * blockDim.x + threadIdx.x) >> 5;
    int lane = threadIdx.x & 31;
    if (node >= N_NODES) return;

    float4 sc = make_float4(1.f, 1.f, 1.f, 1.f);
    float4 sh = make_float4(0.f, 0.f, 0.f, 0.f);
    if (!raw) {
        sc = *(const float4*)(scale + lane * 4);
        sh = *(const float4*)(shift + lane * 4);
    }

    // self term
    float4 acc = *(const float4*)(z + (size_t)node * DIM + lane * 4);
    if (!raw) {
        acc.x = fmaxf(fmaf(acc.x, sc.x, sh.x), 0.f);
        acc.y = fmaxf(fmaf(acc.y, sc.y, sh.y), 0.f);
        acc.z = fmaxf(fmaf(acc.z, sc.z, sh.z), 0.f);
        acc.w = fmaxf(fmaf(acc.w, sc.w, sh.w), 0.f);
    }

    int beg = g_beg[node];
    int d = g_deg[node];
    for (int j0 = 0; j0 < d; j0 += 32) {
        int myidx = (j0 + lane < d) ? g_csrsrc[beg + j0 + lane] : 0;
        int cnt = min(32, d - j0);
        for (int k = 0; k < cnt; k++) {
            int s = __shfl_sync(0xffffffff, myidx, k);
            float4 v = *(const float4*)(z + (size_t)s * DIM + lane * 4);
            if (!raw) {
                v.x = fmaxf(fmaf(v.x, sc.x, sh.x), 0.f);
                v.y = fmaxf(fmaf(v.y, sc.y, sh.y), 0.f);
                v.z = fmaxf(fmaf(v.z, sc.z, sh.z), 0.f);
                v.w = fmaxf(fmaf(v.w, sc.w, sh.w), 0.f);
            }
            acc.x += v.x; acc.y += v.y; acc.z += v.z; acc.w += v.w;
        }
    }
    *(float4*)(agg + (size_t)node * DIM + lane * 4) = acc;
}

// ---------------- tf32 helpers ----------------
__device__ __forceinline__ unsigned cvt_tf32(float x) {
    unsigned r;
    asm("cvt.rna.tf32.f32 %0, %1;" : "=r"(r) : "f"(x));
    return r;
}

__device__ __forceinline__ void mma_tf32(float* d, const unsigned* a, const unsigned* b) {
    asm volatile(
        "mma.sync.aligned.m16n8k8.row.col.f32.tf32.tf32.f32 "
        "{%0,%1,%2,%3}, {%4,%5,%6,%7}, {%8,%9}, {%0,%1,%2,%3};"
        : "+f"(d[0]), "+f"(d[1]), "+f"(d[2]), "+f"(d[3])
        : "r"(a[0]), "r"(a[1]), "r"(a[2]), "r"(a[3]), "r"(b[0]), "r"(b[1]));
}

__global__ void wcvt_kernel(const float* __restrict__ W1s, const float* __restrict__ W2s) {
    const int total = N_LAYERS * DIM * DIM;
    int i = blockIdx.x * blockDim.x + threadIdx.x;
    if (i < total) {
        g_wcvt[i] = cvt_tf32(W1s[i]);
        g_wcvt[total + i] = cvt_tf32(W2s[i]);
    }
}

// ---------------- persistent tf32 tensor-core GEMM ----------------
__global__ void mlp_gemm_tc(const float* __restrict__ A,
                            const unsigned* __restrict__ Wc,
                            const float* __restrict__ bias,
                            float* __restrict__ C,
                            int M, int do_relu,
                            float* __restrict__ stats,
                            int ntiles) {
    extern __shared__ unsigned smu[];
    unsigned* Ws = smu;                                 // 128 x 132 (tf32 bits)
    float* Ab0 = (float*)(smu + DIM * WS_STRIDE);       // 64 x 132 raw fp32
    float* Ab1 = Ab0 + TILE_ROWS * AS_STRIDE;
    const int tid = threadIdx.x;
    const int warp = tid >> 5;
    const int lane = tid & 31;

    for (int i = tid; i < DIM * DIM / 4; i += 256) {
        int r = i >> 5, c4 = (i & 31) * 4;
        uint4 v = *(const uint4*)(Wc + r * DIM + c4);
        unsigned* p = Ws + r * WS_STRIDE + c4;
        p[0] = v.x; p[1] = v.y; p[2] = v.z; p[3] = v.w;
    }

    const int wm = (warp >> 2) * 32;
    const int wn = (warp & 3) * 32;
    const int lq = lane >> 2;
    const int lr = lane & 3;

    int t = blockIdx.x;
    {
        float* dstb = Ab0;
        if (t < ntiles) {
            const float* base = A + (size_t)t * TILE_ROWS * DIM;
            int maxrow = M - t * TILE_ROWS;
#pragma unroll
            for (int q = 0; q < 8; q++) {
                int idx = q * 256 + tid;
                int r = idx >> 5, c4 = (idx & 31) * 4;
                unsigned saddr = (unsigned)__cvta_generic_to_shared(dstb + r * AS_STRIDE + c4);
                const float* g = base + (r < maxrow ? r : 0) * DIM + c4;
                int sz = (r < maxrow) ? 16 : 0;
                asm volatile("cp.async.cg.shared.global [%0], [%1], 16, %2;"
                             :: "r"(saddr), "l"(g), "r"(sz));
            }
        }
        asm volatile("cp.async.commit_group;");
    }

    int buf = 0;
    for (; t < ntiles; t += GEMM_BLOCKS) {
        int nxt = t + GEMM_BLOCKS;
        float* dstb = buf ? Ab0 : Ab1;
        if (nxt < ntiles) {
            const float* base = A + (size_t)nxt * TILE_ROWS * DIM;
            int maxrow = M - nxt * TILE_ROWS;
#pragma unroll
            for (int q = 0; q < 8; q++) {
                int idx = q * 256 + tid;
                int r = idx >> 5, c4 = (idx & 31) * 4;
                unsigned saddr = (unsigned)__cvta_generic_to_shared(dstb + r * AS_STRIDE + c4);
                const float* g = base + (r < maxrow ? r : 0) * DIM + c4;
                int sz = (r < maxrow) ? 16 : 0;
                asm volatile("cp.async.cg.shared.global [%0], [%1], 16, %2;"
                             :: "r"(saddr), "l"(g), "r"(sz));
            }
        }
        asm volatile("cp.async.commit_group;");
        asm volatile("cp.async.wait_group 1;");
        __syncthreads();

        const float* Ac = buf ? Ab1 : Ab0;
        const int row0 = t * TILE_ROWS;

        float acc[2][4][4];
#pragma unroll
        for (int i = 0; i < 2; i++)
#pragma unroll
            for (int j = 0; j < 4; j++)
#pragma unroll
                for (int q = 0; q < 4; q++) acc[i][j][q] = 0.f;

#pragma unroll
        for (int ks = 0; ks < 16; ks++) {
            const int k0 = ks * 8;
            unsigned af[2][4];
#pragma unroll
            for (int i = 0; i < 2; i++) {
                const float* base = Ac + (wm + i * 16 + lq) * AS_STRIDE + k0 + lr;
                af[i][0] = cvt_tf32(base[0]);
                af[i][1] = cvt_tf32(base[8 * AS_STRIDE]);
                af[i][2] = cvt_tf32(base[4]);
                af[i][3] = cvt_tf32(base[8 * AS_STRIDE + 4]);
            }
            unsigned bf[4][2];
#pragma unroll
            for (int j = 0; j < 4; j++) {
                const unsigned* base = Ws + (k0 + lr) * WS_STRIDE + wn + j * 8 + lq;
                bf[j][0] = base[0];
                bf[j][1] = base[4 * WS_STRIDE];
            }
#pragma unroll
            for (int i = 0; i < 2; i++)
#pragma unroll
                for (int j = 0; j < 4; j++) mma_tf32(acc[i][j], af[i], bf[j]);
        }

        float csum[8], csq[8];
#pragma unroll
        for (int k = 0; k < 8; k++) { csum[k] = 0.f; csq[k] = 0.f; }

#pragma unroll
        for (int i = 0; i < 2; i++) {
#pragma unroll
            for (int j = 0; j < 4; j++) {
                int col = wn + j * 8 + lr * 2;
                float b0 = bias[col], b1 = bias[col + 1];
                int r0 = row0 + wm + i * 16 + lq;
                float2 v0, v1;
                v0.x = acc[i][j][0] + b0; v0.y = acc[i][j][1] + b1;
                v1.x = acc[i][j][2] + b0; v1.y = acc[i][j][3] + b1;
                if (do_relu) {
                    v0.x = fmaxf(v0.x, 0.f); v0.y = fmaxf(v0.y, 0.f);
                    v1.x = fmaxf(v1.x, 0.f); v1.y = fmaxf(v1.y, 0.f);
                }
                bool ok0 = r0 < M, ok1 = r0 + 8 < M;
                if (ok0) *(float2*)(C + (size_t)r0 * DIM + col) = v0;
                if (ok1) *(float2*)(C + (size_t)(r0 + 8) * DIM + col) = v1;
                if (stats) {
                    csum[j * 2]     += (ok0 ? v0.x : 0.f) + (ok1 ? v1.x : 0.f);
                    csum[j * 2 + 1] += (ok0 ? v0.y : 0.f) + (ok1 ? v1.y : 0.f);
                    csq[j * 2]      += (ok0 ? v0.x * v0.x : 0.f) + (ok1 ? v1.x * v1.x : 0.f);
                    csq[j * 2 + 1]  += (ok0 ? v0.y * v0.y : 0.f) + (ok1 ? v1.y * v1.y : 0.f);
                }
            }
        }
        if (stats) {
#pragma unroll
            for (int k = 0; k < 8; k++) {
#pragma unroll
                for (int off = 4; off < 32; off <<= 1) {
                    csum[k] += __shfl_xor_sync(0xffffffff, csum[k], off);
                    csq[k]  += __shfl_xor_sync(0xffffffff, csq[k], off);
                }
            }
            if (lq == 0) {
#pragma unroll
                for (int k = 0; k < 8; k++) {
                    int col = wn + (k >> 1) * 8 + lr * 2 + (k & 1);
                    atomicAdd(&stats[col], csum[k]);
                    atomicAdd(&stats[DIM + col], csq[k]);
                }
            }
        }
        __syncthreads();
        buf ^= 1;
    }
}

// ---------------- BatchNorm finalize ----------------
__global__ void bn_finalize(const float* __restrict__ stats,
                            const float* __restrict__ gamma,
                            const float* __restrict__ beta,
                            float* scale, float* shift) {
    int c = threadIdx.x;
    float mean = stats[c] / (float)N_NODES;
    float var = stats[DIM + c] / (float)N_NODES - mean * mean;
    float sc = gamma[c] * rsqrtf(var + BN_EPS);
    scale[c] = sc;
    shift[c] = beta[c] - mean * sc;
}

// ---------------- global_add_pool with fused bnrelu ----------------
__global__ void pool_kernel(const float* __restrict__ z,
                            const float* __restrict__ scale,
                            const float* __restrict__ shift,
                            const int* __restrict__ batch,
                            float* __restrict__ pool) {
    int node = (blockIdx.x * blockDim.x + threadIdx.x) >> 5;
    int lane = threadIdx.x & 31;
    if (node >= N_NODES) return;
    int b = batch[node];
    float4 v = *(const float4*)(z + (size_t)node * DIM + lane * 4);
    float4 sc = *(const float4*)(scale + lane * 4);
    float4 sh = *(const float4*)(shift + lane * 4);
    v.x = fmaxf(fmaf(v.x, sc.x, sh.x), 0.f);
    v.y = fmaxf(fmaf(v.y, sc.y, sh.y), 0.f);
    v.z = fmaxf(fmaf(v.z, sc.z, sh.z), 0.f);
    v.w = fmaxf(fmaf(v.w, sc.w, sh.w), 0.f);
    float* p = pool + (size_t)b * DIM + lane * 4;
    asm volatile("red.global.add.v4.f32 [%0], {%1,%2,%3,%4};"
                 :: "l"(p), "f"(v.x), "f"(v.y), "f"(v.z), "f"(v.w) : "memory");
}

// ---------------- head MLP ----------------
__global__ void head_kernel(const float* __restrict__ pool,
                            const float* __restrict__ Wh1, const float* __restrict__ bh1,
                            const float* __restrict__ Wh2, const float* __restrict__ bh2,
                            float* __restrict__ out) {
    __shared__ float row[DIM];
    __shared__ float hid[DIM];
    int g = blockIdx.x;
    int t = threadIdx.x;
    row[t] = pool[(size_t)g * DIM + t];
    __syncthreads();
    float acc = bh1[t];
    for (int k = 0; k < DIM; k++) acc = fmaf(row[k], Wh1[k * DIM + t], acc);
    hid[t] = fmaxf(acc, 0.f);
    __syncthreads();
    if (t < OUT_DIM) {
        float o = bh2[t];
        for (int k = 0; k < DIM; k++) o = fmaf(hid[k], Wh2[k * OUT_DIM + t], o);
        out[(size_t)g * OUT_DIM + t] = o;
    }
}

// ---------------- launch ----------------
extern "C" void kernel_launch(void* const* d_in, const int* in_sizes, int n_in,
                              void* d_out, int out_size) {
    const float* x     = (const float*)d_in[0];
    const int*   ei    = (const int*)d_in[1];
    const int*   batch = (const int*)d_in[2];
    const float* W1s = (const float*)d_in[3];
    const float* b1s = (const float*)d_in[4];
    const float* W2s = (const float*)d_in[5];
    const float* b2s = (const float*)d_in[6];
    const float* gammas = (const float*)d_in[7];
    const float* betas  = (const float*)d_in[8];
    const float* Wh1 = (const float*)d_in[9];
    const float* bh1 = (const float*)d_in[10];
    const float* Wh2 = (const float*)d_in[11];
    const float* bh2 = (const float*)d_in[12];
    float* out = (float*)d_out;

    float *aggp, *zp, *tp, *statsp, *scalep, *shiftp, *poolp;
    unsigned* wcp;
    int* degp;
    cudaGetSymbolAddress((void**)&aggp, g_agg);
    cudaGetSymbolAddress((void**)&zp, g_z);
    cudaGetSymbolAddress((void**)&tp, g_t);
    cudaGetSymbolAddress((void**)&statsp, g_stats);
    cudaGetSymbolAddress((void**)&scalep, g_scale);
    cudaGetSymbolAddress((void**)&shiftp, g_shift);
    cudaGetSymbolAddress((void**)&poolp, g_pool);
    cudaGetSymbolAddress((void**)&wcp, g_wcvt);
    cudaGetSymbolAddress((void**)&degp, g_deg);

    const int* src = ei;
    const int* dst = ei + N_EDGES;

    const int ntiles = (N_NODES + TILE_ROWS - 1) / TILE_ROWS;
    const int gemmSmem = (DIM * WS_STRIDE + 2 * TILE_ROWS * AS_STRIDE) * sizeof(unsigned);
    const int wTotal = N_LAYERS * DIM * DIM;
    const int edgeB = (N_EDGES + 255) / 256;
    const int aggBlocks = (N_NODES * 32 + 255) / 256;
    cudaFuncSetAttribute(mlp_gemm_tc, cudaFuncAttributeMaxDynamicSharedMemorySize, gemmSmem);

    // ---- one-time per call: weight convert + CSR build ----
    wcvt_kernel<<<(wTotal + 255) / 256, 256>>>(W1s, W2s);
    zero_int_kernel<<<(N_NODES + 255) / 256, 256>>>(degp, N_NODES);
    count_kernel<<<edgeB, 256>>>(dst);
    scan_block_kernel<<<SCAN_NB, SCAN_B>>>();
    scan_totals_kernel<<<1, 32>>>();
    scan_add_kernel<<<SCAN_NB, SCAN_B>>>();
    fill_kernel<<<edgeB, 256>>>(src, dst);

    for (int l = 0; l < N_LAYERS; l++) {
        const float* zin = (l == 0) ? x : zp;
        int raw = (l == 0) ? 1 : 0;
        // agg = h + sum_neighbors h, h = bnrelu(z_prev) on the fly
        agg_kernel<<<aggBlocks, 256>>>(zin, scalep, shiftp, raw, aggp);
        // t = relu(agg @ W1 + b1)
        mlp_gemm_tc<<<GEMM_BLOCKS, 256, gemmSmem>>>(
            aggp, wcp + (size_t)l * DIM * DIM,
            b1s + (size_t)l * DIM, tp, N_NODES, 1, nullptr, ntiles);
        // z = t @ W2 + b2, fused column stats
        zero_kernel<<<1, 64>>>(statsp, 64);
        mlp_gemm_tc<<<GEMM_BLOCKS, 256, gemmSmem>>>(
            tp, wcp + (size_t)(wTotal + l * DIM * DIM),
            b2s + (size_t)l * DIM, zp, N_NODES, 0, statsp, ntiles);
        bn_finalize<<<1, DIM>>>(statsp, gammas + (size_t)l * DIM, betas + (size_t)l * DIM,
                                scalep, shiftp);
    }

    // global_add_pool of bnrelu(z_final)
    const int pool4 = N_GRAPHS * DIM / 4;
    zero_kernel<<<(pool4 + 255) / 256, 256>>>(poolp, pool4);
    pool_kernel<<<aggBlocks, 256>>>(zp, scalep, shiftp, batch, poolp);

    // head
    head_kernel<<<N_GRAPHS, DIM>>>(poolp, Wh1, bh1, Wh2, bh2, out);
}

// round 9
// speedup vs baseline: 2.6188x; 1.0399x over previous
#include <cuda_runtime.h>
#include <cuda_bf16.h>
#include <math.h>

#define N_NODES 100000
#define N_EDGES 1600000
#define N_GRAPHS 2048
#define DIM 128
#define OUT_DIM 12
#define N_LAYERS 5
#define BN_EPS 1e-5f
#define TILE_ROWS 64
#define AS_STRIDE 132
#define WS_STRIDE 132
#define GEMM_BLOCKS 148
#define SCAN_B 1024
#define SCAN_NB ((N_NODES + SCAN_B - 1) / SCAN_B)   // 98

// ---------------- scratch (device globals; no allocation allowed) ----------------
__device__ __align__(16) float g_agg[(size_t)N_NODES * DIM];
__device__ __align__(16) float g_z[(size_t)N_NODES * DIM];
__device__ __align__(16) float g_t[(size_t)N_NODES * DIM];
__device__ __align__(16) float g_stats[2 * DIM];
__device__ __align__(16) float g_scale[DIM];
__device__ __align__(16) float g_shift[DIM];
__device__ __align__(16) float g_pool[(size_t)N_GRAPHS * DIM];
__device__ __align__(16) unsigned g_wcvt[(size_t)2 * N_LAYERS * DIM * DIM];
// CSR scratch
__device__ __align__(16) int g_deg[N_NODES];
__device__ __align__(16) int g_beg[N_NODES];
__device__ __align__(16) int g_cur[N_NODES];
__device__ __align__(16) int g_bsum[SCAN_NB];
__device__ __align__(16) int g_csrsrc[N_EDGES];

// ---------------- small utility kernels ----------------
__global__ void zero_kernel(float* p, int n4) {
    int i = blockIdx.x * blockDim.x + threadIdx.x;
    if (i < n4) ((float4*)p)[i] = make_float4(0.f, 0.f, 0.f, 0.f);
}

__global__ void zero_int_kernel(int* p, int n) {
    int i = blockIdx.x * blockDim.x + threadIdx.x;
    if (i < n) p[i] = 0;
}

// ---------------- CSR build ----------------
__global__ void count_kernel(const int* __restrict__ dst) {
    int i = blockIdx.x * blockDim.x + threadIdx.x;
    if (i < N_EDGES) atomicAdd(&g_deg[dst[i]], 1);
}

__global__ void scan_block_kernel() {
    __shared__ int sm[SCAN_B];
    int tid = threadIdx.x;
    int i = blockIdx.x * SCAN_B + tid;
    int v = (i < N_NODES) ? g_deg[i] : 0;
    sm[tid] = v;
    __syncthreads();
    for (int off = 1; off < SCAN_B; off <<= 1) {
        int t = (tid >= off) ? sm[tid - off] : 0;
        __syncthreads();
        sm[tid] += t;
        __syncthreads();
    }
    if (i < N_NODES) g_beg[i] = sm[tid] - v;   // exclusive within block
    if (tid == SCAN_B - 1) g_bsum[blockIdx.x] = sm[tid];
}

__global__ void scan_totals_kernel() {
    if (threadIdx.x == 0) {
        int run = 0;
        for (int i = 0; i < SCAN_NB; i++) { int t = g_bsum[i]; g_bsum[i] = run; run += t; }
    }
}

__global__ void scan_add_kernel() {
    int i = blockIdx.x * SCAN_B + threadIdx.x;
    if (i < N_NODES) {
        int b = g_beg[i] + g_bsum[blockIdx.x];
        g_beg[i] = b;
        g_cur[i] = b;
    }
}

__global__ void fill_kernel(const int* __restrict__ src, const int* __restrict__ dst) {
    int i = blockIdx.x * blockDim.x + threadIdx.x;
    if (i < N_EDGES) {
        int slot = atomicAdd(&g_cur[dst[i]], 1);
        g_csrsrc[slot] = src[i];
    }
}

// ---------------- fused aggregation: agg[n] = h[n] + sum_{e: dst=n} h[src] ------
// h = bnrelu(z) applied on the fly (raw=1 for layer 0: h = z). One warp per node.
// Inner gather unrolled x4 for MLP=4 (independent L2 loads in flight).
__device__ __forceinline__ float4 bnrelu4(float4 v, float4 sc, float4 sh, int raw) {
    if (!raw) {
        v.x = fmaxf(fmaf(v.x, sc.x, sh.x), 0.f);
        v.y = fmaxf(fmaf(v.y, sc.y, sh.y), 0.f);
        v.z = fmaxf(fmaf(v.z, sc.z, sh.z), 0.f);
        v.w = fmaxf(fmaf(v.w, sc.w, sh.w), 0.f);
    }
    return v;
}

__global__ void agg_kernel(const float* __restrict__ z,
                           const float* __restrict__ scale,
                           const float* __restrict__ shift,
                           int raw,
                           float* __restrict__ agg) {
    int node = (blockIdx.x * blockDim.x + threadIdx.x) >> 5;
    int lane = threadIdx.x & 31;
    if (node >= N_NODES) return;

    float4 sc = make_float4(1.f, 1.f, 1.f, 1.f);
    float4 sh = make_float4(0.f, 0.f, 0.f, 0.f);
    if (!raw) {
        sc = *(const float4*)(scale + lane * 4);
        sh = *(const float4*)(shift + lane * 4);
    }

    // self term
    float4 acc = bnrelu4(*(const float4*)(z + (size_t)node * DIM + lane * 4), sc, sh, raw);

    const int beg = g_beg[node];
    const int d = g_deg[node];
    const size_t laneoff = lane * 4;

    for (int j0 = 0; j0 < d; j0 += 32) {
        int myidx = (j0 + lane < d) ? g_csrsrc[beg + j0 + lane] : 0;
        int cnt = min(32, d - j0);
        int k = 0;
        for (; k + 4 <= cnt; k += 4) {
            int s0 = __shfl_sync(0xffffffff, myidx, k);
            int s1 = __shfl_sync(0xffffffff, myidx, k + 1);
            int s2 = __shfl_sync(0xffffffff, myidx, k + 2);
            int s3 = __shfl_sync(0xffffffff, myidx, k + 3);
            float4 v0 = *(const float4*)(z + (size_t)s0 * DIM + laneoff);
            float4 v1 = *(const float4*)(z + (size_t)s1 * DIM + laneoff);
            float4 v2 = *(const float4*)(z + (size_t)s2 * DIM + laneoff);
            float4 v3 = *(const float4*)(z + (size_t)s3 * DIM + laneoff);
            v0 = bnrelu4(v0, sc, sh, raw);
            v1 = bnrelu4(v1, sc, sh, raw);
            v2 = bnrelu4(v2, sc, sh, raw);
            v3 = bnrelu4(v3, sc, sh, raw);
            acc.x += v0.x + v1.x + v2.x + v3.x;
            acc.y += v0.y + v1.y + v2.y + v3.y;
            acc.z += v0.z + v1.z + v2.z + v3.z;
            acc.w += v0.w + v1.w + v2.w + v3.w;
        }
        for (; k < cnt; k++) {
            int s = __shfl_sync(0xffffffff, myidx, k);
            float4 v = bnrelu4(*(const float4*)(z + (size_t)s * DIM + laneoff), sc, sh, raw);
            acc.x += v.x; acc.y += v.y; acc.z += v.z; acc.w += v.w;
        }
    }
    *(float4*)(agg + (size_t)node * DIM + laneoff) = acc;
}

// ---------------- tf32 helpers ----------------
__device__ __forceinline__ unsigned cvt_tf32(float x) {
    unsigned r;
    asm("cvt.rna.tf32.f32 %0, %1;" : "=r"(r) : "f"(x));
    return r;
}

__device__ __forceinline__ void mma_tf32(float* d, const unsigned* a, const unsigned* b) {
    asm volatile(
        "mma.sync.aligned.m16n8k8.row.col.f32.tf32.tf32.f32 "
        "{%0,%1,%2,%3}, {%4,%5,%6,%7}, {%8,%9}, {%0,%1,%2,%3};"
        : "+f"(d[0]), "+f"(d[1]), "+f"(d[2]), "+f"(d[3])
        : "r"(a[0]), "r"(a[1]), "r"(a[2]), "r"(a[3]), "r"(b[0]), "r"(b[1]));
}

__global__ void wcvt_kernel(const float* __restrict__ W1s, const float* __restrict__ W2s) {
    const int total = N_LAYERS * DIM * DIM;
    int i = blockIdx.x * blockDim.x + threadIdx.x;
    if (i < total) {
        g_wcvt[i] = cvt_tf32(W1s[i]);
        g_wcvt[total + i] = cvt_tf32(W2s[i]);
    }
}

// ---------------- persistent tf32 tensor-core GEMM ----------------
__global__ void mlp_gemm_tc(const float* __restrict__ A,
                            const unsigned* __restrict__ Wc,
                            const float* __restrict__ bias,
                            float* __restrict__ C,
                            int M, int do_relu,
                            float* __restrict__ stats,
                            int ntiles) {
    extern __shared__ unsigned smu[];
    unsigned* Ws = smu;                                 // 128 x 132 (tf32 bits)
    float* Ab0 = (float*)(smu + DIM * WS_STRIDE);       // 64 x 132 raw fp32
    float* Ab1 = Ab0 + TILE_ROWS * AS_STRIDE;
    const int tid = threadIdx.x;
    const int warp = tid >> 5;
    const int lane = tid & 31;

    for (int i = tid; i < DIM * DIM / 4; i += 256) {
        int r = i >> 5, c4 = (i & 31) * 4;
        uint4 v = *(const uint4*)(Wc + r * DIM + c4);
        unsigned* p = Ws + r * WS_STRIDE + c4;
        p[0] = v.x; p[1] = v.y; p[2] = v.z; p[3] = v.w;
    }

    const int wm = (warp >> 2) * 32;
    const int wn = (warp & 3) * 32;
    const int lq = lane >> 2;
    const int lr = lane & 3;

    int t = blockIdx.x;
    {
        float* dstb = Ab0;
        if (t < ntiles) {
            const float* base = A + (size_t)t * TILE_ROWS * DIM;
            int maxrow = M - t * TILE_ROWS;
#pragma unroll
            for (int q = 0; q < 8; q++) {
                int idx = q * 256 + tid;
                int r = idx >> 5, c4 = (idx & 31) * 4;
                unsigned saddr = (unsigned)__cvta_generic_to_shared(dstb + r * AS_STRIDE + c4);
                const float* g = base + (r < maxrow ? r : 0) * DIM + c4;
                int sz = (r < maxrow) ? 16 : 0;
                asm volatile("cp.async.cg.shared.global [%0], [%1], 16, %2;"
                             :: "r"(saddr), "l"(g), "r"(sz));
            }
        }
        asm volatile("cp.async.commit_group;");
    }

    int buf = 0;
    for (; t < ntiles; t += GEMM_BLOCKS) {
        int nxt = t + GEMM_BLOCKS;
        float* dstb = buf ? Ab0 : Ab1;
        if (nxt < ntiles) {
            const float* base = A + (size_t)nxt * TILE_ROWS * DIM;
            int maxrow = M - nxt * TILE_ROWS;
#pragma unroll
            for (int q = 0; q < 8; q++) {
                int idx = q * 256 + tid;
                int r = idx >> 5, c4 = (idx & 31) * 4;
                unsigned saddr = (unsigned)__cvta_generic_to_shared(dstb + r * AS_STRIDE + c4);
                const float* g = base + (r < maxrow ? r : 0) * DIM + c4;
                int sz = (r < maxrow) ? 16 : 0;
                asm volatile("cp.async.cg.shared.global [%0], [%1], 16, %2;"
                             :: "r"(saddr), "l"(g), "r"(sz));
            }
        }
        asm volatile("cp.async.commit_group;");
        asm volatile("cp.async.wait_group 1;");
        __syncthreads();

        const float* Ac = buf ? Ab1 : Ab0;
        const int row0 = t * TILE_ROWS;

        float acc[2][4][4];
#pragma unroll
        for (int i = 0; i < 2; i++)
#pragma unroll
            for (int j = 0; j < 4; j++)
#pragma unroll
                for (int q = 0; q < 4; q++) acc[i][j][q] = 0.f;

#pragma unroll
        for (int ks = 0; ks < 16; ks++) {
            const int k0 = ks * 8;
            unsigned af[2][4];
#pragma unroll
            for (int i = 0; i < 2; i++) {
                const float* base = Ac + (wm + i * 16 + lq) * AS_STRIDE + k0 + lr;
                af[i][0] = cvt_tf32(base[0]);
                af[i][1] = cvt_tf32(base[8 * AS_STRIDE]);
                af[i][2] = cvt_tf32(base[4]);
                af[i][3] = cvt_tf32(base[8 * AS_STRIDE + 4]);
            }
            unsigned bf[4][2];
#pragma unroll
            for (int j = 0; j < 4; j++) {
                const unsigned* base = Ws + (k0 + lr) * WS_STRIDE + wn + j * 8 + lq;
                bf[j][0] = base[0];
                bf[j][1] = base[4 * WS_STRIDE];
            }
#pragma unroll
            for (int i = 0; i < 2; i++)
#pragma unroll
                for (int j = 0; j < 4; j++) mma_tf32(acc[i][j], af[i], bf[j]);
        }

        float csum[8], csq[8];
#pragma unroll
        for (int k = 0; k < 8; k++) { csum[k] = 0.f; csq[k] = 0.f; }

#pragma unroll
        for (int i = 0; i < 2; i++) {
#pragma unroll
            for (int j = 0; j < 4; j++) {
                int col = wn + j * 8 + lr * 2;
                float b0 = bias[col], b1 = bias[col + 1];
                int r0 = row0 + wm + i * 16 + lq;
                float2 v0, v1;
                v0.x = acc[i][j][0] + b0; v0.y = acc[i][j][1] + b1;
                v1.x = acc[i][j][2] + b0; v1.y = acc[i][j][3] + b1;
                if (do_relu) {
                    v0.x = fmaxf(v0.x, 0.f); v0.y = fmaxf(v0.y, 0.f);
                    v1.x = fmaxf(v1.x, 0.f); v1.y = fmaxf(v1.y, 0.f);
                }
                bool ok0 = r0 < M, ok1 = r0 + 8 < M;
                if (ok0) *(float2*)(C + (size_t)r0 * DIM + col) = v0;
                if (ok1) *(float2*)(C + (size_t)(r0 + 8) * DIM + col) = v1;
                if (stats) {
                    csum[j * 2]     += (ok0 ? v0.x : 0.f) + (ok1 ? v1.x : 0.f);
                    csum[j * 2 + 1] += (ok0 ? v0.y : 0.f) + (ok1 ? v1.y : 0.f);
                    csq[j * 2]      += (ok0 ? v0.x * v0.x : 0.f) + (ok1 ? v1.x * v1.x : 0.f);
                    csq[j * 2 + 1]  += (ok0 ? v0.y * v0.y : 0.f) + (ok1 ? v1.y * v1.y : 0.f);
                }
            }
        }
        if (stats) {
#pragma unroll
            for (int k = 0; k < 8; k++) {
#pragma unroll
                for (int off = 4; off < 32; off <<= 1) {
                    csum[k] += __shfl_xor_sync(0xffffffff, csum[k], off);
                    csq[k]  += __shfl_xor_sync(0xffffffff, csq[k], off);
                }
            }
            if (lq == 0) {
#pragma unroll
                for (int k = 0; k < 8; k++) {
                    int col = wn + (k >> 1) * 8 + lr * 2 + (k & 1);
                    atomicAdd(&stats[col], csum[k]);
                    atomicAdd(&stats[DIM + col], csq[k]);
                }
            }
        }
        __syncthreads();
        buf ^= 1;
    }
}

// ---------------- BatchNorm finalize ----------------
__global__ void bn_finalize(const float* __restrict__ stats,
                            const float* __restrict__ gamma,
                            const float* __restrict__ beta,
                            float* scale, float* shift) {
    int c = threadIdx.x;
    float mean = stats[c] / (float)N_NODES;
    float var = stats[DIM + c] / (float)N_NODES - mean * mean;
    float sc = gamma[c] * rsqrtf(var + BN_EPS);
    scale[c] = sc;
    shift[c] = beta[c] - mean * sc;
}

// ---------------- global_add_pool with fused bnrelu ----------------
__global__ void pool_kernel(const float* __restrict__ z,
                            const float* __restrict__ scale,
                            const float* __restrict__ shift,
                            const int* __restrict__ batch,
                            float* __restrict__ pool) {
    int node = (blockIdx.x * blockDim.x + threadIdx.x) >> 5;
    int lane = threadIdx.x & 31;
    if (node >= N_NODES) return;
    int b = batch[node];
    float4 v = *(const float4*)(z + (size_t)node * DIM + lane * 4);
    float4 sc = *(const float4*)(scale + lane * 4);
    float4 sh = *(const float4*)(shift + lane * 4);
    v.x = fmaxf(fmaf(v.x, sc.x, sh.x), 0.f);
    v.y = fmaxf(fmaf(v.y, sc.y, sh.y), 0.f);
    v.z = fmaxf(fmaf(v.z, sc.z, sh.z), 0.f);
    v.w = fmaxf(fmaf(v.w, sc.w, sh.w), 0.f);
    float* p = pool + (size_t)b * DIM + lane * 4;
    asm volatile("red.global.add.v4.f32 [%0], {%1,%2,%3,%4};"
                 :: "l"(p), "f"(v.x), "f"(v.y), "f"(v.z), "f"(v.w) : "memory");
}

// ---------------- head MLP ----------------
__global__ void head_kernel(const float* __restrict__ pool,
                            const float* __restrict__ Wh1, const float* __restrict__ bh1,
                            const float* __restrict__ Wh2, const float* __restrict__ bh2,
                            float* __restrict__ out) {
    __shared__ float row[DIM];
    __shared__ float hid[DIM];
    int g = blockIdx.x;
    int t = threadIdx.x;
    row[t] = pool[(size_t)g * DIM + t];
    __syncthreads();
    float acc = bh1[t];
    for (int k = 0; k < DIM; k++) acc = fmaf(row[k], Wh1[k * DIM + t], acc);
    hid[t] = fmaxf(acc, 0.f);
    __syncthreads();
    if (t < OUT_DIM) {
        float o = bh2[t];
        for (int k = 0; k < DIM; k++) o = fmaf(hid[k], Wh2[k * OUT_DIM + t], o);
        out[(size_t)g * OUT_DIM + t] = o;
    }
}

// ---------------- launch ----------------
extern "C" void kernel_launch(void* const* d_in, const int* in_sizes, int n_in,
                              void* d_out, int out_size) {
    const float* x     = (const float*)d_in[0];
    const int*   ei    = (const int*)d_in[1];
    const int*   batch = (const int*)d_in[2];
    const float* W1s = (const float*)d_in[3];
    const float* b1s = (const float*)d_in[4];
    const float* W2s = (const float*)d_in[5];
    const float* b2s = (const float*)d_in[6];
    const float* gammas = (const float*)d_in[7];
    const float* betas  = (const float*)d_in[8];
    const float* Wh1 = (const float*)d_in[9];
    const float* bh1 = (const float*)d_in[10];
    const float* Wh2 = (const float*)d_in[11];
    const float* bh2 = (const float*)d_in[12];
    float* out = (float*)d_out;

    float *aggp, *zp, *tp, *statsp, *scalep, *shiftp, *poolp;
    unsigned* wcp;
    int* degp;
    cudaGetSymbolAddress((void**)&aggp, g_agg);
    cudaGetSymbolAddress((void**)&zp, g_z);
    cudaGetSymbolAddress((void**)&tp, g_t);
    cudaGetSymbolAddress((void**)&statsp, g_stats);
    cudaGetSymbolAddress((void**)&scalep, g_scale);
    cudaGetSymbolAddress((void**)&shiftp, g_shift);
    cudaGetSymbolAddress((void**)&poolp, g_pool);
    cudaGetSymbolAddress((void**)&wcp, g_wcvt);
    cudaGetSymbolAddress((void**)&degp, g_deg);

    const int* src = ei;
    const int* dst = ei + N_EDGES;

    const int ntiles = (N_NODES + TILE_ROWS - 1) / TILE_ROWS;
    const int gemmSmem = (DIM * WS_STRIDE + 2 * TILE_ROWS * AS_STRIDE) * sizeof(unsigned);
    const int wTotal = N_LAYERS * DIM * DIM;
    const int edgeB = (N_EDGES + 255) / 256;
    const int aggBlocks = (N_NODES * 32 + 255) / 256;
    cudaFuncSetAttribute(mlp_gemm_tc, cudaFuncAttributeMaxDynamicSharedMemorySize, gemmSmem);

    // ---- one-time per call: weight convert + CSR build ----
    wcvt_kernel<<<(wTotal + 255) / 256, 256>>>(W1s, W2s);
    zero_int_kernel<<<(N_NODES + 255) / 256, 256>>>(degp, N_NODES);
    count_kernel<<<edgeB, 256>>>(dst);
    scan_block_kernel<<<SCAN_NB, SCAN_B>>>();
    scan_totals_kernel<<<1, 32>>>();
    scan_add_kernel<<<SCAN_NB, SCAN_B>>>();
    fill_kernel<<<edgeB, 256>>>(src, dst);

    for (int l = 0; l < N_LAYERS; l++) {
        const float* zin = (l == 0) ? x : zp;
        int raw = (l == 0) ? 1 : 0;
        // agg = h + sum_neighbors h, h = bnrelu(z_prev) on the fly
        agg_kernel<<<aggBlocks, 256>>>(zin, scalep, shiftp, raw, aggp);
        // t = relu(agg @ W1 + b1)
        mlp_gemm_tc<<<GEMM_BLOCKS, 256, gemmSmem>>>(
            aggp, wcp + (size_t)l * DIM * DIM,
            b1s + (size_t)l * DIM, tp, N_NODES, 1, nullptr, ntiles);
        // z = t @ W2 + b2, fused column stats
        zero_kernel<<<1, 64>>>(statsp, 64);
        mlp_gemm_tc<<<GEMM_BLOCKS, 256, gemmSmem>>>(
            tp, wcp + (size_t)(wTotal + l * DIM * DIM),
            b2s + (size_t)l * DIM, zp, N_NODES, 0, statsp, ntiles);
        bn_finalize<<<1, DIM>>>(statsp, gammas + (size_t)l * DIM, betas + (size_t)l * DIM,
                                scalep, shiftp);
    }

    // global_add_pool of bnrelu(z_final)
    const int pool4 = N_GRAPHS * DIM / 4;
    zero_kernel<<<(pool4 + 255) / 256, 256>>>(poolp, pool4);
    pool_kernel<<<aggBlocks, 256>>>(zp, scalep, shiftp, batch, poolp);

    // head
    head_kernel<<<N_GRAPHS, DIM>>>(poolp, Wh1, bh1, Wh2, bh2, out);
}

// round 12
// speedup vs baseline: 3.1132x; 1.1888x over previous
#include <cuda_runtime.h>
#include <cuda_bf16.h>
#include <math.h>

#define N_NODES 100000
#define N_EDGES 1600000
#define N_GRAPHS 2048
#define DIM 128
#define OUT_DIM 12
#define N_LAYERS 5
#define BN_EPS 1e-5f
#define TILE_ROWS 64
#define AS_STRIDE 132
#define WS_STRIDE 132
#define GEMM_BLOCKS 148
#define SCAN_B 1024
#define SCAN_NB ((N_NODES + SCAN_B - 1) / SCAN_B)   // 98

// ---------------- scratch (device globals; no allocation allowed) ----------------
__device__ __align__(16) float g_agg[(size_t)N_NODES * DIM];
__device__ __align__(16) float g_z[(size_t)N_NODES * DIM];
__device__ __align__(16) float g_stats[2 * DIM];
__device__ __align__(16) float g_scale[DIM];
__device__ __align__(16) float g_shift[DIM];
__device__ __align__(16) float g_pool[(size_t)N_GRAPHS * DIM];
__device__ __align__(16) unsigned g_wcvt[(size_t)2 * N_LAYERS * DIM * DIM];
// CSR scratch
__device__ __align__(16) int g_deg[N_NODES];
__device__ __align__(16) int g_beg[N_NODES];
__device__ __align__(16) int g_cur[N_NODES];
__device__ __align__(16) int g_bsum[SCAN_NB];
__device__ __align__(16) int g_csrsrc[N_EDGES];

// ---------------- small utility kernels ----------------
__global__ void zero_kernel(float* p, int n4) {
    int i = blockIdx.x * blockDim.x + threadIdx.x;
    if (i < n4) ((float4*)p)[i] = make_float4(0.f, 0.f, 0.f, 0.f);
}

__global__ void zero_int_kernel(int* p, int n) {
    int i = blockIdx.x * blockDim.x + threadIdx.x;
    if (i < n) p[i] = 0;
}

// ---------------- CSR build ----------------
__global__ void count_kernel(const int* __restrict__ dst) {
    int i = blockIdx.x * blockDim.x + threadIdx.x;
    if (i < N_EDGES) atomicAdd(&g_deg[dst[i]], 1);
}

__global__ void scan_block_kernel() {
    __shared__ int sm[SCAN_B];
    int tid = threadIdx.x;
    int i = blockIdx.x * SCAN_B + tid;
    int v = (i < N_NODES) ? g_deg[i] : 0;
    sm[tid] = v;
    __syncthreads();
    for (int off = 1; off < SCAN_B; off <<= 1) {
        int t = (tid >= off) ? sm[tid - off] : 0;
        __syncthreads();
        sm[tid] += t;
        __syncthreads();
    }
    if (i < N_NODES) g_beg[i] = sm[tid] - v;
    if (tid == SCAN_B - 1) g_bsum[blockIdx.x] = sm[tid];
}

__global__ void scan_totals_kernel() {
    if (threadIdx.x == 0) {
        int run = 0;
        for (int i = 0; i < SCAN_NB; i++) { int t = g_bsum[i]; g_bsum[i] = run; run += t; }
    }
}

__global__ void scan_add_kernel() {
    int i = blockIdx.x * SCAN_B + threadIdx.x;
    if (i < N_NODES) {
        int b = g_beg[i] + g_bsum[blockIdx.x];
        g_beg[i] = b;
        g_cur[i] = b;
    }
}

__global__ void fill_kernel(const int* __restrict__ src, const int* __restrict__ dst) {
    int i = blockIdx.x * blockDim.x + threadIdx.x;
    if (i < N_EDGES) {
        int slot = atomicAdd(&g_cur[dst[i]], 1);
        g_csrsrc[slot] = src[i];
    }
}

// ---------------- fused aggregation ----------------
__device__ __forceinline__ float4 bnrelu4(float4 v, float4 sc, float4 sh, int raw) {
    if (!raw) {
        v.x = fmaxf(fmaf(v.x, sc.x, sh.x), 0.f);
        v.y = fmaxf(fmaf(v.y, sc.y, sh.y), 0.f);
        v.z = fmaxf(fmaf(v.z, sc.z, sh.z), 0.f);
        v.w = fmaxf(fmaf(v.w, sc.w, sh.w), 0.f);
    }
    return v;
}

__global__ void agg_kernel(const float* __restrict__ z,
                           const float* __restrict__ scale,
                           const float* __restrict__ shift,
                           int raw,
                           float* __restrict__ agg) {
    int node = (blockIdx.x * blockDim.x + threadIdx.x) >> 5;
    int lane = threadIdx.x & 31;
    if (node >= N_NODES) return;

    float4 sc = make_float4(1.f, 1.f, 1.f, 1.f);
    float4 sh = make_float4(0.f, 0.f, 0.f, 0.f);
    if (!raw) {
        sc = *(const float4*)(scale + lane * 4);
        sh = *(const float4*)(shift + lane * 4);
    }

    float4 acc = bnrelu4(*(const float4*)(z + (size_t)node * DIM + lane * 4), sc, sh, raw);

    const int beg = g_beg[node];
    const int d = g_deg[node];
    const size_t laneoff = lane * 4;

    for (int j0 = 0; j0 < d; j0 += 32) {
        int myidx = (j0 + lane < d) ? g_csrsrc[beg + j0 + lane] : 0;
        int cnt = min(32, d - j0);
        int k = 0;
        for (; k + 4 <= cnt; k += 4) {
            int s0 = __shfl_sync(0xffffffff, myidx, k);
            int s1 = __shfl_sync(0xffffffff, myidx, k + 1);
            int s2 = __shfl_sync(0xffffffff, myidx, k + 2);
            int s3 = __shfl_sync(0xffffffff, myidx, k + 3);
            float4 v0 = *(const float4*)(z + (size_t)s0 * DIM + laneoff);
            float4 v1 = *(const float4*)(z + (size_t)s1 * DIM + laneoff);
            float4 v2 = *(const float4*)(z + (size_t)s2 * DIM + laneoff);
            float4 v3 = *(const float4*)(z + (size_t)s3 * DIM + laneoff);
            v0 = bnrelu4(v0, sc, sh, raw);
            v1 = bnrelu4(v1, sc, sh, raw);
            v2 = bnrelu4(v2, sc, sh, raw);
            v3 = bnrelu4(v3, sc, sh, raw);
            acc.x += v0.x + v1.x + v2.x + v3.x;
            acc.y += v0.y + v1.y + v2.y + v3.y;
            acc.z += v0.z + v1.z + v2.z + v3.z;
            acc.w += v0.w + v1.w + v2.w + v3.w;
        }
        for (; k < cnt; k++) {
            int s = __shfl_sync(0xffffffff, myidx, k);
            float4 v = bnrelu4(*(const float4*)(z + (size_t)s * DIM + laneoff), sc, sh, raw);
            acc.x += v.x; acc.y += v.y; acc.z += v.z; acc.w += v.w;
        }
    }
    *(float4*)(agg + (size_t)node * DIM + laneoff) = acc;
}

// ---------------- tf32 helpers ----------------
__device__ __forceinline__ unsigned cvt_tf32(float x) {
    unsigned r;
    asm("cvt.rna.tf32.f32 %0, %1;" : "=r"(r) : "f"(x));
    return r;
}

__device__ __forceinline__ void mma_tf32(float* d, const unsigned* a, const unsigned* b) {
    asm volatile(
        "mma.sync.aligned.m16n8k8.row.col.f32.tf32.tf32.f32 "
        "{%0,%1,%2,%3}, {%4,%5,%6,%7}, {%8,%9}, {%0,%1,%2,%3};"
        : "+f"(d[0]), "+f"(d[1]), "+f"(d[2]), "+f"(d[3])
        : "r"(a[0]), "r"(a[1]), "r"(a[2]), "r"(a[3]), "r"(b[0]), "r"(b[1]));
}

__global__ void wcvt_kernel(const float* __restrict__ W1s, const float* __restrict__ W2s) {
    const int total = N_LAYERS * DIM * DIM;
    int i = blockIdx.x * blockDim.x + threadIdx.x;
    if (i < total) {
        g_wcvt[i] = cvt_tf32(W1s[i]);
        g_wcvt[total + i] = cvt_tf32(W2s[i]);
    }
}

// ---------------- fused 2-GEMM persistent kernel ----------------
// z = relu(A @ W1 + b1) @ W2 + b2, with fused column stats. W1 and W2 are
// smem-resident; intermediate T lives in smem only. A prefetch for the next
// tile overlaps mainloop2 (A buffer is dead after mainloop1).
__global__ void __launch_bounds__(256, 1)
mlp_fused_tc(const float* __restrict__ A,
             const unsigned* __restrict__ W1c,
             const unsigned* __restrict__ W2c,
             const float* __restrict__ b1,
             const float* __restrict__ b2,
             float* __restrict__ C,
             int M,
             float* __restrict__ stats,
             int ntiles) {
    extern __shared__ unsigned smu[];
    unsigned* W1s = smu;                                 // 128 x 132
    unsigned* W2s = smu + DIM * WS_STRIDE;               // 128 x 132
    float* Ab = (float*)(smu + 2 * DIM * WS_STRIDE);     // 64 x 132
    float* Tb = Ab + TILE_ROWS * AS_STRIDE;              // 64 x 132
    const int tid = threadIdx.x;
    const int warp = tid >> 5;
    const int lane = tid & 31;

    for (int i = tid; i < DIM * DIM / 4; i += 256) {
        int r = i >> 5, c4 = (i & 31) * 4;
        uint4 v1 = *(const uint4*)(W1c + r * DIM + c4);
        uint4 v2 = *(const uint4*)(W2c + r * DIM + c4);
        unsigned* p1 = W1s + r * WS_STRIDE + c4;
        unsigned* p2 = W2s + r * WS_STRIDE + c4;
        p1[0] = v1.x; p1[1] = v1.y; p1[2] = v1.z; p1[3] = v1.w;
        p2[0] = v2.x; p2[1] = v2.y; p2[2] = v2.z; p2[3] = v2.w;
    }

    const int wm = (warp >> 2) * 32;
    const int wn = (warp & 3) * 32;
    const int lq = lane >> 2;
    const int lr = lane & 3;

    // prefetch first A tile
    int t = blockIdx.x;
    if (t < ntiles) {
        const float* base = A + (size_t)t * TILE_ROWS * DIM;
        int maxrow = M - t * TILE_ROWS;
#pragma unroll
        for (int q = 0; q < 8; q++) {
            int idx = q * 256 + tid;
            int r = idx >> 5, c4 = (idx & 31) * 4;
            unsigned saddr = (unsigned)__cvta_generic_to_shared(Ab + r * AS_STRIDE + c4);
            const float* g = base + (r < maxrow ? r : 0) * DIM + c4;
            int sz = (r < maxrow) ? 16 : 0;
            asm volatile("cp.async.cg.shared.global [%0], [%1], 16, %2;"
                         :: "r"(saddr), "l"(g), "r"(sz));
        }
    }
    asm volatile("cp.async.commit_group;");

    for (; t < ntiles; t += GEMM_BLOCKS) {
        asm volatile("cp.async.wait_group 0;");
        __syncthreads();   // A ready (W ready on first pass; prev Tb reads done)

        const int row0 = t * TILE_ROWS;

        // ---- mainloop 1: acc1 = A @ W1 ----
        float acc1[2][4][4];
#pragma unroll
        for (int i = 0; i < 2; i++)
#pragma unroll
            for (int j = 0; j < 4; j++)
#pragma unroll
                for (int q = 0; q < 4; q++) acc1[i][j][q] = 0.f;

#pragma unroll
        for (int ks = 0; ks < 16; ks++) {
            const int k0 = ks * 8;
            unsigned af[2][4];
#pragma unroll
            for (int i = 0; i < 2; i++) {
                const float* base = Ab + (wm + i * 16 + lq) * AS_STRIDE + k0 + lr;
                af[i][0] = cvt_tf32(base[0]);
                af[i][1] = cvt_tf32(base[8 * AS_STRIDE]);
                af[i][2] = cvt_tf32(base[4]);
                af[i][3] = cvt_tf32(base[8 * AS_STRIDE + 4]);
            }
            unsigned bf[4][2];
#pragma unroll
            for (int j = 0; j < 4; j++) {
                const unsigned* base = W1s + (k0 + lr) * WS_STRIDE + wn + j * 8 + lq;
                bf[j][0] = base[0];
                bf[j][1] = base[4 * WS_STRIDE];
            }
#pragma unroll
            for (int i = 0; i < 2; i++)
#pragma unroll
                for (int j = 0; j < 4; j++) mma_tf32(acc1[i][j], af[i], bf[j]);
        }
        __syncthreads();   // all warps done reading Ab

        // prefetch next A tile into Ab (overlaps with epilogue1 + mainloop2)
        int nxt = t + GEMM_BLOCKS;
        if (nxt < ntiles) {
            const float* base = A + (size_t)nxt * TILE_ROWS * DIM;
            int maxrow = M - nxt * TILE_ROWS;
#pragma unroll
            for (int q = 0; q < 8; q++) {
                int idx = q * 256 + tid;
                int r = idx >> 5, c4 = (idx & 31) * 4;
                unsigned saddr = (unsigned)__cvta_generic_to_shared(Ab + r * AS_STRIDE + c4);
                const float* g = base + (r < maxrow ? r : 0) * DIM + c4;
                int sz = (r < maxrow) ? 16 : 0;
                asm volatile("cp.async.cg.shared.global [%0], [%1], 16, %2;"
                             :: "r"(saddr), "l"(g), "r"(sz));
            }
        }
        asm volatile("cp.async.commit_group;");

        // ---- epilogue 1: T = relu(acc1 + b1) into smem ----
#pragma unroll
        for (int i = 0; i < 2; i++) {
#pragma unroll
            for (int j = 0; j < 4; j++) {
                int col = wn + j * 8 + lr * 2;
                float c0 = b1[col], c1 = b1[col + 1];
                int rl = wm + i * 16 + lq;
                float2 v0, v1;
                v0.x = fmaxf(acc1[i][j][0] + c0, 0.f);
                v0.y = fmaxf(acc1[i][j][1] + c1, 0.f);
                v1.x = fmaxf(acc1[i][j][2] + c0, 0.f);
                v1.y = fmaxf(acc1[i][j][3] + c1, 0.f);
                *(float2*)(Tb + rl * AS_STRIDE + col) = v0;
                *(float2*)(Tb + (rl + 8) * AS_STRIDE + col) = v1;
            }
        }
        __syncthreads();   // T ready

        // ---- mainloop 2: acc2 = T @ W2 ----
        float acc2[2][4][4];
#pragma unroll
        for (int i = 0; i < 2; i++)
#pragma unroll
            for (int j = 0; j < 4; j++)
#pragma unroll
                for (int q = 0; q < 4; q++) acc2[i][j][q] = 0.f;

#pragma unroll
        for (int ks = 0; ks < 16; ks++) {
            const int k0 = ks * 8;
            unsigned af[2][4];
#pragma unroll
            for (int i = 0; i < 2; i++) {
                const float* base = Tb + (wm + i * 16 + lq) * AS_STRIDE + k0 + lr;
                af[i][0] = cvt_tf32(base[0]);
                af[i][1] = cvt_tf32(base[8 * AS_STRIDE]);
                af[i][2] = cvt_tf32(base[4]);
                af[i][3] = cvt_tf32(base[8 * AS_STRIDE + 4]);
            }
            unsigned bf[4][2];
#pragma unroll
            for (int j = 0; j < 4; j++) {
                const unsigned* base = W2s + (k0 + lr) * WS_STRIDE + wn + j * 8 + lq;
                bf[j][0] = base[0];
                bf[j][1] = base[4 * WS_STRIDE];
            }
#pragma unroll
            for (int i = 0; i < 2; i++)
#pragma unroll
                for (int j = 0; j < 4; j++) mma_tf32(acc2[i][j], af[i], bf[j]);
        }

        // ---- epilogue 2: z = acc2 + b2, store + fused stats ----
        float csum[8], csq[8];
#pragma unroll
        for (int k = 0; k < 8; k++) { csum[k] = 0.f; csq[k] = 0.f; }

#pragma unroll
        for (int i = 0; i < 2; i++) {
#pragma unroll
            for (int j = 0; j < 4; j++) {
                int col = wn + j * 8 + lr * 2;
                float c0 = b2[col], c1 = b2[col + 1];
                int r0 = row0 + wm + i * 16 + lq;
                float2 v0, v1;
                v0.x = acc2[i][j][0] + c0; v0.y = acc2[i][j][1] + c1;
                v1.x = acc2[i][j][2] + c0; v1.y = acc2[i][j][3] + c1;
                bool ok0 = r0 < M, ok1 = r0 + 8 < M;
                if (ok0) *(float2*)(C + (size_t)r0 * DIM + col) = v0;
                if (ok1) *(float2*)(C + (size_t)(r0 + 8) * DIM + col) = v1;
                csum[j * 2]     += (ok0 ? v0.x : 0.f) + (ok1 ? v1.x : 0.f);
                csum[j * 2 + 1] += (ok0 ? v0.y : 0.f) + (ok1 ? v1.y : 0.f);
                csq[j * 2]      += (ok0 ? v0.x * v0.x : 0.f) + (ok1 ? v1.x * v1.x : 0.f);
                csq[j * 2 + 1]  += (ok0 ? v0.y * v0.y : 0.f) + (ok1 ? v1.y * v1.y : 0.f);
            }
        }
#pragma unroll
        for (int k = 0; k < 8; k++) {
#pragma unroll
            for (int off = 4; off < 32; off <<= 1) {
                csum[k] += __shfl_xor_sync(0xffffffff, csum[k], off);
                csq[k]  += __shfl_xor_sync(0xffffffff, csq[k], off);
            }
        }
        if (lq == 0) {
#pragma unroll
            for (int k = 0; k < 8; k++) {
                int col = wn + (k >> 1) * 8 + lr * 2 + (k & 1);
                atomicAdd(&stats[col], csum[k]);
                atomicAdd(&stats[DIM + col], csq[k]);
            }
        }
        __syncthreads();   // Tb reads done before next tile's epilogue1 rewrites it
    }
}

// ---------------- BatchNorm finalize ----------------
__global__ void bn_finalize(const float* __restrict__ stats,
                            const float* __restrict__ gamma,
                            const float* __restrict__ beta,
                            float* scale, float* shift) {
    int c = threadIdx.x;
    float mean = stats[c] / (float)N_NODES;
    float var = stats[DIM + c] / (float)N_NODES - mean * mean;
    float sc = gamma[c] * rsqrtf(var + BN_EPS);
    scale[c] = sc;
    shift[c] = beta[c] - mean * sc;
}

// ---------------- global_add_pool with fused bnrelu ----------------
__global__ void pool_kernel(const float* __restrict__ z,
                            const float* __restrict__ scale,
                            const float* __restrict__ shift,
                            const int* __restrict__ batch,
                            float* __restrict__ pool) {
    int node = (blockIdx.x * blockDim.x + threadIdx.x) >> 5;
    int lane = threadIdx.x & 31;
    if (node >= N_NODES) return;
    int b = batch[node];
    float4 v = *(const float4*)(z + (size_t)node * DIM + lane * 4);
    float4 sc = *(const float4*)(scale + lane * 4);
    float4 sh = *(const float4*)(shift + lane * 4);
    v.x = fmaxf(fmaf(v.x, sc.x, sh.x), 0.f);
    v.y = fmaxf(fmaf(v.y, sc.y, sh.y), 0.f);
    v.z = fmaxf(fmaf(v.z, sc.z, sh.z), 0.f);
    v.w = fmaxf(fmaf(v.w, sc.w, sh.w), 0.f);
    float* p = pool + (size_t)b * DIM + lane * 4;
    asm volatile("red.global.add.v4.f32 [%0], {%1,%2,%3,%4};"
                 :: "l"(p), "f"(v.x), "f"(v.y), "f"(v.z), "f"(v.w) : "memory");
}

// ---------------- head MLP ----------------
__global__ void head_kernel(const float* __restrict__ pool,
                            const float* __restrict__ Wh1, const float* __restrict__ bh1,
                            const float* __restrict__ Wh2, const float* __restrict__ bh2,
                            float* __restrict__ out) {
    __shared__ float row[DIM];
    __shared__ float hid[DIM];
    int g = blockIdx.x;
    int t = threadIdx.x;
    row[t] = pool[(size_t)g * DIM + t];
    __syncthreads();
    float acc = bh1[t];
    for (int k = 0; k < DIM; k++) acc = fmaf(row[k], Wh1[k * DIM + t], acc);
    hid[t] = fmaxf(acc, 0.f);
    __syncthreads();
    if (t < OUT_DIM) {
        float o = bh2[t];
        for (int k = 0; k < DIM; k++) o = fmaf(hid[k], Wh2[k * OUT_DIM + t], o);
        out[(size_t)g * OUT_DIM + t] = o;
    }
}

// ---------------- launch ----------------
extern "C" void kernel_launch(void* const* d_in, const int* in_sizes, int n_in,
                              void* d_out, int out_size) {
    const float* x     = (const float*)d_in[0];
    const int*   ei    = (const int*)d_in[1];
    const int*   batch = (const int*)d_in[2];
    const float* W1s = (const float*)d_in[3];
    const float* b1s = (const float*)d_in[4];
    const float* W2s = (const float*)d_in[5];
    const float* b2s = (const float*)d_in[6];
    const float* gammas = (const float*)d_in[7];
    const float* betas  = (const float*)d_in[8];
    const float* Wh1 = (const float*)d_in[9];
    const float* bh1 = (const float*)d_in[10];
    const float* Wh2 = (const float*)d_in[11];
    const float* bh2 = (const float*)d_in[12];
    float* out = (float*)d_out;

    float *aggp, *zp, *statsp, *scalep, *shiftp, *poolp;
    unsigned* wcp;
    int* degp;
    cudaGetSymbolAddress((void**)&aggp, g_agg);
    cudaGetSymbolAddress((void**)&zp, g_z);
    cudaGetSymbolAddress((void**)&statsp, g_stats);
    cudaGetSymbolAddress((void**)&scalep, g_scale);
    cudaGetSymbolAddress((void**)&shiftp, g_shift);
    cudaGetSymbolAddress((void**)&poolp, g_pool);
    cudaGetSymbolAddress((void**)&wcp, g_wcvt);
    cudaGetSymbolAddress((void**)&degp, g_deg);

    const int* src = ei;
    const int* dst = ei + N_EDGES;

    const int ntiles = (N_NODES + TILE_ROWS - 1) / TILE_ROWS;
    const int fusedSmem = (2 * DIM * WS_STRIDE + 2 * TILE_ROWS * AS_STRIDE) * sizeof(unsigned);
    const int wTotal = N_LAYERS * DIM * DIM;
    const int edgeB = (N_EDGES + 255) / 256;
    const int aggBlocks = (N_NODES * 32 + 255) / 256;
    cudaFuncSetAttribute(mlp_fused_tc, cudaFuncAttributeMaxDynamicSharedMemorySize, fusedSmem);

    // ---- one-time per call: weight convert + CSR build ----
    wcvt_kernel<<<(wTotal + 255) / 256, 256>>>(W1s, W2s);
    zero_int_kernel<<<(N_NODES + 255) / 256, 256>>>(degp, N_NODES);
    count_kernel<<<edgeB, 256>>>(dst);
    scan_block_kernel<<<SCAN_NB, SCAN_B>>>();
    scan_totals_kernel<<<1, 32>>>();
    scan_add_kernel<<<SCAN_NB, SCAN_B>>>();
    fill_kernel<<<edgeB, 256>>>(src, dst);

    for (int l = 0; l < N_LAYERS; l++) {
        const float* zin = (l == 0) ? x : zp;
        int raw = (l == 0) ? 1 : 0;
        // agg = h + sum_neighbors h, h = bnrelu(z_prev) on the fly
        agg_kernel<<<aggBlocks, 256>>>(zin, scalep, shiftp, raw, aggp);
        // z = relu(agg @ W1 + b1) @ W2 + b2, fused stats (T never hits gmem)
        zero_kernel<<<1, 64>>>(statsp, 64);
        mlp_fused_tc<<<GEMM_BLOCKS, 256, fusedSmem>>>(
            aggp,
            wcp + (size_t)l * DIM * DIM,
            wcp + (size_t)(wTotal + l * DIM * DIM),
            b1s + (size_t)l * DIM, b2s + (size_t)l * DIM,
            zp, N_NODES, statsp, ntiles);
        bn_finalize<<<1, DIM>>>(statsp, gammas + (size_t)l * DIM, betas + (size_t)l * DIM,
                                scalep, shiftp);
    }

    // global_add_pool of bnrelu(z_final)
    const int pool4 = N_GRAPHS * DIM / 4;
    zero_kernel<<<(pool4 + 255) / 256, 256>>>(poolp, pool4);
    pool_kernel<<<aggBlocks, 256>>>(zp, scalep, shiftp, batch, poolp);

    // head
    head_kernel<<<N_GRAPHS, DIM>>>(poolp, Wh1, bh1, Wh2, bh2, out);
}